// round 2
// baseline (speedup 1.0000x reference)
#include <cuda_runtime.h>
#include <math.h>

#define NN 4096
#define NF 128
#define DD 64
#define EE 32768
#define BB 32
#define NK 65   // intervals = 64 breakpoints + 1

// ------------------------- scratch (device globals) -------------------------
__device__ float g_tmp[NN*DD];
__device__ float g_bufA[NN*DD];
__device__ float g_bufB[NN*DD];
__device__ float g_conv[NN*DD];
__device__ float g_agg[NN*DD];
__device__ float g_gi[NN*192];
__device__ float g_gh[NN*192];
__device__ float g_deg[NN];
__device__ float g_P[NK*4096];
__device__ float g_Q[NK*4096];
__device__ float g_w[64], g_c[64], g_t[64];
__device__ int   g_rank[64];
__device__ int   g_cnt[NK], g_off[NK+1], g_cur[NK];
__device__ int   g_ke[EE], g_eord[EE];
__device__ float g_e[NN];
__device__ float g_q[BB*DD], g_hh[BB*DD], g_cc[BB*DD];
__device__ float g_qstar[BB*2*DD];
__device__ float g_gates[BB*4*DD];
__device__ int   g_bstart[BB+1];
__device__ float g_y1[BB*DD], g_y2[BB*DD];

__device__ __forceinline__ float sigm(float x) { return 1.0f/(1.0f+expf(-x)); }

// ------------------------- init / misc -------------------------
__global__ void k_zero_init() {
    int i = blockIdx.x*blockDim.x + threadIdx.x; // 4096 threads
    if (i < NN)      g_deg[i]   = 0.0f;
    if (i < BB*2*DD) g_qstar[i] = 0.0f;
    if (i < BB*DD) { g_hh[i] = 0.0f; g_cc[i] = 0.0f; }
}

__global__ void k_zero_agg() {
    int i = blockIdx.x*blockDim.x + threadIdx.x; // 262144 threads
    if (i < NN*DD) g_agg[i] = 0.0f;
    if (i < NK)    g_cnt[i] = 0;
}

__global__ void k_deg(const int* __restrict__ eidx) {
    int e = blockIdx.x*blockDim.x + threadIdx.x;
    if (e < EE) atomicAdd(&g_deg[eidx[EE + e]], 1.0f);
}

__global__ void k_bstart(const int* __restrict__ bm) {
    int b = threadIdx.x;
    if (b > BB) return;
    int lo = 0, hi = NN;
    while (lo < hi) { int mid = (lo+hi)>>1; if (bm[mid] < b) lo = mid+1; else hi = mid; }
    g_bstart[b] = lo;
}

// ------------------------- generic GEMM (OUT=64) -------------------------
template<int IN, bool RELU>
__global__ __launch_bounds__(256) void k_gemm64(const float* __restrict__ X,
                                                const float* __restrict__ W,
                                                const float* __restrict__ b,
                                                float* __restrict__ Y, int nrows) {
    __shared__ float sW[IN*64];
    __shared__ float sX[16*IN];
    __shared__ float sB[64];
    int t = threadIdx.x;
    for (int i = t; i < IN*64; i += 256) sW[i] = W[i];
    if (t < 64) sB[t] = b[t];
    int r0 = blockIdx.x * 16;
    int nr = nrows - r0; if (nr > 16) nr = 16;
    for (int i = t; i < nr*IN; i += 256) sX[i] = X[r0*IN + i];
    __syncthreads();
    int o = t & 63;
    for (int m = (t >> 6); m < nr; m += 4) {
        float acc = sB[o];
        const float* xr = &sX[m*IN];
        #pragma unroll 16
        for (int i = 0; i < IN; i++) acc = fmaf(xr[i], sW[i*64+o], acc);
        if (RELU) acc = fmaxf(acc, 0.0f);
        Y[(r0+m)*64 + o] = acc;
    }
}

// ------------------------- GEMM to 192 (GRU gi/gh) -------------------------
__global__ __launch_bounds__(192) void k_gemm192(const float* __restrict__ X,
                                                 const float* __restrict__ W,
                                                 const float* __restrict__ b,
                                                 float* __restrict__ Y) {
    __shared__ float sX[16*64];
    __shared__ float sW[32*192];
    int t = threadIdx.x; // 192
    int r0 = blockIdx.x * 16;
    for (int i = t; i < 16*64; i += 192) sX[i] = X[r0*64 + i];
    float acc[16];
    float bv = b[t];
    #pragma unroll
    for (int m = 0; m < 16; m++) acc[m] = bv;
    for (int kt = 0; kt < 64; kt += 32) {
        __syncthreads();
        for (int i = t; i < 32*192; i += 192) sW[i] = W[kt*192 + i];
        __syncthreads();
        #pragma unroll
        for (int i = 0; i < 32; i++) {
            float wv = sW[i*192 + t];
            #pragma unroll
            for (int m = 0; m < 16; m++) acc[m] = fmaf(sX[m*64 + kt + i], wv, acc[m]);
        }
    }
    #pragma unroll
    for (int m = 0; m < 16; m++) Y[(r0+m)*192 + t] = acc[m];
}

// ------------------------- piecewise-linear ENN tables -------------------------
__global__ void k_prep(const float* __restrict__ W1, const float* __restrict__ b1) {
    __shared__ float st[64];
    int g = threadIdx.x; // 64 threads
    float w = W1[g], c = b1[g];
    float tt = (w != 0.0f) ? (-c / w) : __int_as_float(0x7f800000); // +inf sentinel
    st[g] = tt;
    g_w[g] = w; g_c[g] = c; g_t[g] = tt;
    __syncthreads();
    int r = 0;
    for (int j = 0; j < 64; j++) r += (st[j] < tt) ? 1 : 0;
    g_rank[g] = r;
}

__global__ __launch_bounds__(256) void k_buildPQ(const float* __restrict__ W2,
                                                 const float* __restrict__ b2) {
    int k  = blockIdx.x;   // 0..64
    int t0 = threadIdx.x;  // 256
    float p[16], q[16];
    #pragma unroll
    for (int j = 0; j < 16; j++) { p[j] = b2[t0 + j*256]; q[j] = 0.0f; }
    for (int g = 0; g < 64; g++) {
        float w = g_w[g], c = g_c[g];
        bool active = (w > 0.0f) ? (g_rank[g] < k)
                    : ((w < 0.0f) ? (g_rank[g] >= k) : (c > 0.0f));
        if (!active) continue;
        const float* row = W2 + g*4096;
        #pragma unroll
        for (int j = 0; j < 16; j++) {
            float v = row[t0 + j*256];
            p[j] = fmaf(c, v, p[j]);
            q[j] = fmaf(w, v, q[j]);
        }
    }
    #pragma unroll
    for (int j = 0; j < 16; j++) {
        g_P[k*4096 + t0 + j*256] = p[j];
        g_Q[k*4096 + t0 + j*256] = q[j];
    }
}

__global__ void k_ke(const float* __restrict__ ea) {
    __shared__ float st[64];
    if (threadIdx.x < 64) st[threadIdx.x] = g_t[threadIdx.x];
    __syncthreads();
    int e = blockIdx.x*blockDim.x + threadIdx.x;
    if (e >= EE) return;
    float a = ea[e];
    int k = 0;
    #pragma unroll
    for (int j = 0; j < 64; j++) k += (st[j] < a) ? 1 : 0;
    g_ke[e] = k;
    atomicAdd(&g_cnt[k], 1);
}

__global__ void k_scan() {
    if (threadIdx.x == 0) {
        int s = 0;
        for (int k = 0; k < NK; k++) { g_off[k] = s; g_cur[k] = s; s += g_cnt[k]; }
        g_off[NK] = s;
    }
}

__global__ void k_scatter() {
    int e = blockIdx.x*blockDim.x + threadIdx.x;
    if (e >= EE) return;
    int pos = atomicAdd(&g_cur[g_ke[e]], 1);
    g_eord[pos] = e;
}

// warp-per-edge: msg = x_src @ (P_k + a*Q_k), scatter-add into agg
__global__ __launch_bounds__(256) void k_msg(const float* __restrict__ X,
                                             const float* __restrict__ ea,
                                             const int* __restrict__ eidx) {
    __shared__ float sP[4096];
    __shared__ float sQ[4096];
    int k = blockIdx.y;
    int beg = g_off[k], end = g_off[k+1];
    if (beg == end) return;
    const float* P = g_P + k*4096;
    const float* Q = g_Q + k*4096;
    for (int i = threadIdx.x; i < 4096; i += 256) { sP[i] = P[i]; sQ[i] = Q[i]; }
    __syncthreads();
    int warp = threadIdx.x >> 5, lane = threadIdx.x & 31;
    int stride = gridDim.x * 8;
    for (int idx = beg + blockIdx.x*8 + warp; idx < end; idx += stride) {
        int e = g_eord[idx];
        float a = ea[e];
        int s  = eidx[e];
        int dn = eidx[EE + e];
        float x0 = X[s*64 + 2*lane];
        float x1 = X[s*64 + 2*lane + 1];
        float acc0 = 0.0f, acc1 = 0.0f;
        int o0 = lane, o1 = lane + 32;
        #pragma unroll
        for (int i = 0; i < 64; i += 2) {
            float xa = __shfl_sync(0xffffffff, x0, i >> 1);
            float xb = __shfl_sync(0xffffffff, x1, i >> 1);
            acc0 = fmaf(xa, fmaf(a, sQ[i*64+o0], sP[i*64+o0]), acc0);
            acc1 = fmaf(xa, fmaf(a, sQ[i*64+o1], sP[i*64+o1]), acc1);
            acc0 = fmaf(xb, fmaf(a, sQ[(i+1)*64+o0], sP[(i+1)*64+o0]), acc0);
            acc1 = fmaf(xb, fmaf(a, sQ[(i+1)*64+o1], sP[(i+1)*64+o1]), acc1);
        }
        atomicAdd(&g_agg[dn*64 + o0], acc0);
        atomicAdd(&g_agg[dn*64 + o1], acc1);
    }
}

// conv = relu(agg/deg + out@rootW + cb)
__global__ __launch_bounds__(256) void k_conv(const float* __restrict__ X,
                                              const float* __restrict__ W,
                                              const float* __restrict__ cb) {
    __shared__ float sW[64*64];
    __shared__ float sX[16*64];
    __shared__ float sB[64];
    int t = threadIdx.x;
    for (int i = t; i < 4096; i += 256) sW[i] = W[i];
    if (t < 64) sB[t] = cb[t];
    int r0 = blockIdx.x * 16;
    for (int i = t; i < 16*64; i += 256) sX[i] = X[r0*64 + i];
    __syncthreads();
    int o = t & 63;
    for (int m = (t >> 6); m < 16; m += 4) {
        int n = r0 + m;
        float dg = fmaxf(g_deg[n], 1.0f);
        float acc = sB[o] + g_agg[n*64+o] / dg;
        #pragma unroll
        for (int i = 0; i < 64; i++) acc = fmaf(sX[m*64+i], sW[i*64+o], acc);
        g_conv[n*64+o] = fmaxf(acc, 0.0f);
    }
}

__global__ void k_gru(const float* __restrict__ gi, const float* __restrict__ gh,
                      const float* __restrict__ h, float* __restrict__ out) {
    int idx = blockIdx.x*blockDim.x + threadIdx.x;
    int n = idx >> 6, d = idx & 63;
    float ir = gi[n*192+d],     iz = gi[n*192+64+d],  inn = gi[n*192+128+d];
    float hr = gh[n*192+d],     hz = gh[n*192+64+d],  hn  = gh[n*192+128+d];
    float r = sigm(ir + hr);
    float z = sigm(iz + hz);
    float nn = tanhf(inn + r * hn);
    out[idx] = (1.0f - z) * nn + z * h[idx];
}

// ------------------------- Set2Set -------------------------
__global__ __launch_bounds__(256) void k_lstm_gates(const float* __restrict__ Wih,
                                                    const float* __restrict__ Whh,
                                                    const float* __restrict__ bih,
                                                    const float* __restrict__ bhh) {
    __shared__ float sq[BB*128];
    __shared__ float sh[BB*64];
    int t = threadIdx.x;
    for (int i = t; i < BB*128; i += 256) sq[i] = g_qstar[i];
    for (int i = t; i < BB*64;  i += 256) sh[i] = g_hh[i];
    __syncthreads();
    int col = blockIdx.x*32 + (t & 31);
    int m0  = t >> 5;
    float acc[4];
    float bs = bih[col] + bhh[col];
    #pragma unroll
    for (int j = 0; j < 4; j++) acc[j] = bs;
    for (int i = 0; i < 128; i++) {
        float wv = Wih[i*256 + col];
        #pragma unroll
        for (int j = 0; j < 4; j++) acc[j] = fmaf(sq[(m0+8*j)*128 + i], wv, acc[j]);
    }
    for (int i = 0; i < 64; i++) {
        float wv = Whh[i*256 + col];
        #pragma unroll
        for (int j = 0; j < 4; j++) acc[j] = fmaf(sh[(m0+8*j)*64 + i], wv, acc[j]);
    }
    #pragma unroll
    for (int j = 0; j < 4; j++) g_gates[(m0+8*j)*256 + col] = acc[j];
}

__global__ void k_lstm_update() {
    for (int i = threadIdx.x; i < BB*64; i += blockDim.x) {
        int b = i >> 6, d = i & 63;
        float gi_ = g_gates[b*256 + d];
        float gf  = g_gates[b*256 + 64 + d];
        float gg  = g_gates[b*256 + 128 + d];
        float go  = g_gates[b*256 + 192 + d];
        float c = sigm(gf) * g_cc[i] + sigm(gi_) * tanhf(gg);
        float h = sigm(go) * tanhf(c);
        g_cc[i] = c; g_hh[i] = h; g_q[i] = h;
    }
}

__global__ __launch_bounds__(128) void k_attn(const float* __restrict__ X) {
    int b = blockIdx.x;
    int beg = g_bstart[b], end = g_bstart[b+1];
    __shared__ float red[4];
    __shared__ float sq[64];
    __shared__ float sr[128];
    int t = threadIdx.x, warp = t >> 5, lane = t & 31;
    if (t < 64) sq[t] = g_q[b*64 + t];
    __syncthreads();
    // pass 1: e[n] = dot(out[n], q[b]); track max
    float mloc = -3.4e38f;
    for (int n = beg + warp; n < end; n += 4) {
        float v = X[n*64+lane]*sq[lane] + X[n*64+32+lane]*sq[32+lane];
        #pragma unroll
        for (int off = 16; off; off >>= 1) v += __shfl_down_sync(0xffffffff, v, off);
        v = __shfl_sync(0xffffffff, v, 0);
        if (lane == 0) g_e[n] = v;
        mloc = fmaxf(mloc, v);
    }
    if (lane == 0) red[warp] = mloc;
    __syncthreads();
    float m = fmaxf(fmaxf(red[0], red[1]), fmaxf(red[2], red[3]));
    __syncthreads();
    // pass 2: den
    float dloc = 0.0f;
    for (int n = beg + t; n < end; n += 128) dloc += expf(g_e[n] - m);
    sr[t] = dloc;
    __syncthreads();
    if (t < 64) sr[t] += sr[t+64];
    __syncthreads();
    if (t < 32) sr[t] += sr[t+32];
    __syncthreads();
    if (t == 0) { float s = 0.0f; for (int i = 0; i < 32; i++) s += sr[i]; red[0] = s; }
    __syncthreads();
    float den = red[0];
    __syncthreads();
    // pass 3: r_read[d]
    int d = t & 63, half = t >> 6;
    float acc = 0.0f;
    for (int n = beg + half; n < end; n += 2) acc += expf(g_e[n] - m) * X[n*64 + d];
    sr[t] = acc;
    __syncthreads();
    if (t < 64) {
        g_qstar[b*128 + 64 + t] = (sr[t] + sr[t+64]) / den;
        g_qstar[b*128 + t]      = sq[t];
    }
}

__global__ void k_final(const float* __restrict__ W3, const float* __restrict__ b3,
                        float* __restrict__ out) {
    int b = threadIdx.x >> 5, lane = threadIdx.x & 31; // 1024 threads = 32 warps
    float v = g_y1[b*64+lane]*W3[lane] + g_y1[b*64+32+lane]*W3[32+lane];
    #pragma unroll
    for (int off = 16; off; off >>= 1) v += __shfl_down_sync(0xffffffff, v, off);
    if (lane == 0) out[b] = v + b3[0];
}

// ------------------------- host -------------------------
extern "C" void kernel_launch(void* const* d_in, const int* in_sizes, int n_in,
                              void* d_out, int out_size) {
    const float* x         = (const float*)d_in[0];
    const float* edge_attr = (const float*)d_in[1];
    const int*   edge_idx  = (const int*)  d_in[2];
    const int*   batch_map = (const int*)  d_in[3];
    const float* pre_W0 = (const float*)d_in[4];
    const float* pre_b0 = (const float*)d_in[5];
    const float* pre_W1 = (const float*)d_in[6];
    const float* pre_b1 = (const float*)d_in[7];
    const float* pre_W2 = (const float*)d_in[8];
    const float* pre_b2 = (const float*)d_in[9];
    const float* enn_W1 = (const float*)d_in[10];
    const float* enn_b1 = (const float*)d_in[11];
    const float* enn_W2 = (const float*)d_in[12];
    const float* enn_b2 = (const float*)d_in[13];
    const float* root_W = (const float*)d_in[14];
    const float* conv_b = (const float*)d_in[15];
    const float* gru_Wih = (const float*)d_in[16];
    const float* gru_Whh = (const float*)d_in[17];
    const float* gru_bih = (const float*)d_in[18];
    const float* gru_bhh = (const float*)d_in[19];
    const float* s2s_Wih = (const float*)d_in[20];
    const float* s2s_Whh = (const float*)d_in[21];
    const float* s2s_bih = (const float*)d_in[22];
    const float* s2s_bhh = (const float*)d_in[23];
    const float* post_W0 = (const float*)d_in[24];
    const float* post_b0 = (const float*)d_in[25];
    const float* post_W1 = (const float*)d_in[26];
    const float* post_b1 = (const float*)d_in[27];
    const float* post_W2 = (const float*)d_in[28];
    const float* post_b2 = (const float*)d_in[29];
    const float* post_W3 = (const float*)d_in[30];
    const float* post_b3 = (const float*)d_in[31];

    float *tmp, *bufA, *bufB, *conv, *gi, *gh, *qstar, *y1, *y2;
    cudaGetSymbolAddress((void**)&tmp,   g_tmp);
    cudaGetSymbolAddress((void**)&bufA,  g_bufA);
    cudaGetSymbolAddress((void**)&bufB,  g_bufB);
    cudaGetSymbolAddress((void**)&conv,  g_conv);
    cudaGetSymbolAddress((void**)&gi,    g_gi);
    cudaGetSymbolAddress((void**)&gh,    g_gh);
    cudaGetSymbolAddress((void**)&qstar, g_qstar);
    cudaGetSymbolAddress((void**)&y1,    g_y1);
    cudaGetSymbolAddress((void**)&y2,    g_y2);

    k_zero_init<<<16, 256>>>();
    k_deg<<<EE/256, 256>>>(edge_idx);
    k_bstart<<<1, 64>>>(batch_map);

    // pre-MLP
    k_gemm64<128, true><<<NN/16, 256>>>(x,    pre_W0, pre_b0, tmp,  NN);
    k_gemm64<64,  true><<<NN/16, 256>>>(tmp,  pre_W1, pre_b1, bufB, NN);
    k_gemm64<64,  true><<<NN/16, 256>>>(bufB, pre_W2, pre_b2, bufA, NN);

    float* cur = bufA;
    float* nxt = bufB;
    for (int l = 0; l < 3; l++) {
        k_prep<<<1, 64>>>(enn_W1 + l*64, enn_b1 + l*64);
        k_zero_agg<<<NN*DD/256, 256>>>();
        k_ke<<<EE/256, 256>>>(edge_attr);
        k_scan<<<1, 32>>>();
        k_scatter<<<EE/256, 256>>>();
        k_buildPQ<<<NK, 256>>>(enn_W2 + l*64*4096, enn_b2 + l*4096);
        k_msg<<<dim3(8, NK), 256>>>(cur, edge_attr, edge_idx);
        k_conv<<<NN/16, 256>>>(cur, root_W + l*4096, conv_b + l*64);
        k_gemm192<<<NN/16, 192>>>(conv, gru_Wih + l*64*192, gru_bih + l*192, gi);
        k_gemm192<<<NN/16, 192>>>(cur,  gru_Whh + l*64*192, gru_bhh + l*192, gh);
        k_gru<<<NN*DD/256, 256>>>(gi, gh, cur, nxt);
        float* sw = cur; cur = nxt; nxt = sw;
    }

    // Set2Set (3 steps)
    for (int s = 0; s < 3; s++) {
        k_lstm_gates<<<8, 256>>>(s2s_Wih, s2s_Whh, s2s_bih, s2s_bhh);
        k_lstm_update<<<1, 1024>>>();
        k_attn<<<BB, 128>>>(cur);
    }

    // post-MLP
    k_gemm64<128, true><<<2, 256>>>(qstar, post_W0, post_b0, y1, BB);
    k_gemm64<64,  true><<<2, 256>>>(y1,    post_W1, post_b1, y2, BB);
    k_gemm64<64,  true><<<2, 256>>>(y2,    post_W2, post_b2, y1, BB);
    k_final<<<1, 1024>>>(post_W3, post_b3, (float*)d_out);
}

// round 3
// speedup vs baseline: 1.0004x; 1.0004x over previous
#include <cuda_runtime.h>
#include <math.h>

#define NN 4096
#define NF 128
#define DD 64
#define EE 32768
#define BB 32
#define NK 65   // intervals = 64 breakpoints + 1

// ------------------------- scratch (device globals) -------------------------
__device__ float g_tmp[NN*DD];
__device__ float g_bufA[NN*DD];
__device__ float g_bufB[NN*DD];
__device__ float g_conv[NN*DD];
__device__ float g_agg[NN*DD];
__device__ float g_gi[NN*192];
__device__ float g_gh[NN*192];
__device__ float g_deg[NN];
__device__ float g_P[NK*4096];
__device__ float g_Q[NK*4096];
__device__ float g_w[64], g_c[64], g_t[64];
__device__ int   g_rank[64];
__device__ int   g_cnt[NK], g_off[NK+1], g_cur[NK];
__device__ int   g_ke[EE], g_eord[EE];
__device__ float g_e[NN];
__device__ float g_q[BB*DD], g_hh[BB*DD], g_cc[BB*DD];
__device__ float g_qstar[BB*2*DD];
__device__ float g_gates[BB*4*DD];
__device__ int   g_bstart[BB+1];
__device__ float g_y1[BB*DD], g_y2[BB*DD];

__device__ __forceinline__ float sigm(float x) { return 1.0f/(1.0f+expf(-x)); }

// ------------------------- init / misc -------------------------
__global__ void k_zero_init() {
    int i = blockIdx.x*blockDim.x + threadIdx.x; // 4096 threads
    if (i < NN)      g_deg[i]   = 0.0f;
    if (i < BB*2*DD) g_qstar[i] = 0.0f;
    if (i < BB*DD) { g_hh[i] = 0.0f; g_cc[i] = 0.0f; }
}

__global__ void k_zero_agg() {
    int i = blockIdx.x*blockDim.x + threadIdx.x; // 262144 threads
    if (i < NN*DD) g_agg[i] = 0.0f;
    if (i < NK)    g_cnt[i] = 0;
}

__global__ void k_deg(const int* __restrict__ eidx) {
    int e = blockIdx.x*blockDim.x + threadIdx.x;
    if (e < EE) atomicAdd(&g_deg[eidx[EE + e]], 1.0f);
}

__global__ void k_bstart(const int* __restrict__ bm) {
    int b = threadIdx.x;
    if (b > BB) return;
    int lo = 0, hi = NN;
    while (lo < hi) { int mid = (lo+hi)>>1; if (bm[mid] < b) lo = mid+1; else hi = mid; }
    g_bstart[b] = lo;
}

// ------------------------- generic GEMM (OUT=64) -------------------------
template<int IN, bool RELU>
__global__ __launch_bounds__(256) void k_gemm64(const float* __restrict__ X,
                                                const float* __restrict__ W,
                                                const float* __restrict__ b,
                                                float* __restrict__ Y, int nrows) {
    __shared__ float sW[IN*64];
    __shared__ float sX[16*IN];
    __shared__ float sB[64];
    int t = threadIdx.x;
    for (int i = t; i < IN*64; i += 256) sW[i] = W[i];
    if (t < 64) sB[t] = b[t];
    int r0 = blockIdx.x * 16;
    int nr = nrows - r0; if (nr > 16) nr = 16;
    for (int i = t; i < nr*IN; i += 256) sX[i] = X[r0*IN + i];
    __syncthreads();
    int o = t & 63;
    for (int m = (t >> 6); m < nr; m += 4) {
        float acc = sB[o];
        const float* xr = &sX[m*IN];
        #pragma unroll 16
        for (int i = 0; i < IN; i++) acc = fmaf(xr[i], sW[i*64+o], acc);
        if (RELU) acc = fmaxf(acc, 0.0f);
        Y[(r0+m)*64 + o] = acc;
    }
}

// ------------------------- GEMM to 192 (GRU gi/gh) -------------------------
__global__ __launch_bounds__(192) void k_gemm192(const float* __restrict__ X,
                                                 const float* __restrict__ W,
                                                 const float* __restrict__ b,
                                                 float* __restrict__ Y) {
    __shared__ float sX[16*64];
    __shared__ float sW[32*192];
    int t = threadIdx.x; // 192
    int r0 = blockIdx.x * 16;
    for (int i = t; i < 16*64; i += 192) sX[i] = X[r0*64 + i];
    float acc[16];
    float bv = b[t];
    #pragma unroll
    for (int m = 0; m < 16; m++) acc[m] = bv;
    for (int kt = 0; kt < 64; kt += 32) {
        __syncthreads();
        for (int i = t; i < 32*192; i += 192) sW[i] = W[kt*192 + i];
        __syncthreads();
        #pragma unroll
        for (int i = 0; i < 32; i++) {
            float wv = sW[i*192 + t];
            #pragma unroll
            for (int m = 0; m < 16; m++) acc[m] = fmaf(sX[m*64 + kt + i], wv, acc[m]);
        }
    }
    #pragma unroll
    for (int m = 0; m < 16; m++) Y[(r0+m)*192 + t] = acc[m];
}

// ------------------------- piecewise-linear ENN tables -------------------------
__global__ void k_prep(const float* __restrict__ W1, const float* __restrict__ b1) {
    __shared__ float st[64];
    int g = threadIdx.x; // 64 threads
    float w = W1[g], c = b1[g];
    float tt = (w != 0.0f) ? (-c / w) : __int_as_float(0x7f800000); // +inf sentinel
    st[g] = tt;
    g_w[g] = w; g_c[g] = c; g_t[g] = tt;
    __syncthreads();
    int r = 0;
    for (int j = 0; j < 64; j++) r += (st[j] < tt) ? 1 : 0;
    g_rank[g] = r;
}

__global__ __launch_bounds__(256) void k_buildPQ(const float* __restrict__ W2,
                                                 const float* __restrict__ b2) {
    int k  = blockIdx.x;   // 0..64
    int t0 = threadIdx.x;  // 256
    float p[16], q[16];
    #pragma unroll
    for (int j = 0; j < 16; j++) { p[j] = b2[t0 + j*256]; q[j] = 0.0f; }
    for (int g = 0; g < 64; g++) {
        float w = g_w[g], c = g_c[g];
        bool active = (w > 0.0f) ? (g_rank[g] < k)
                    : ((w < 0.0f) ? (g_rank[g] >= k) : (c > 0.0f));
        if (!active) continue;
        const float* row = W2 + g*4096;
        #pragma unroll
        for (int j = 0; j < 16; j++) {
            float v = row[t0 + j*256];
            p[j] = fmaf(c, v, p[j]);
            q[j] = fmaf(w, v, q[j]);
        }
    }
    #pragma unroll
    for (int j = 0; j < 16; j++) {
        g_P[k*4096 + t0 + j*256] = p[j];
        g_Q[k*4096 + t0 + j*256] = q[j];
    }
}

__global__ void k_ke(const float* __restrict__ ea) {
    __shared__ float st[64];
    if (threadIdx.x < 64) st[threadIdx.x] = g_t[threadIdx.x];
    __syncthreads();
    int e = blockIdx.x*blockDim.x + threadIdx.x;
    if (e >= EE) return;
    float a = ea[e];
    int k = 0;
    #pragma unroll
    for (int j = 0; j < 64; j++) k += (st[j] < a) ? 1 : 0;
    g_ke[e] = k;
    atomicAdd(&g_cnt[k], 1);
}

__global__ void k_scan() {
    if (threadIdx.x == 0) {
        int s = 0;
        for (int k = 0; k < NK; k++) { g_off[k] = s; g_cur[k] = s; s += g_cnt[k]; }
        g_off[NK] = s;
    }
}

__global__ void k_scatter() {
    int e = blockIdx.x*blockDim.x + threadIdx.x;
    if (e >= EE) return;
    int pos = atomicAdd(&g_cur[g_ke[e]], 1);
    g_eord[pos] = e;
}

// warp-per-edge: msg = x_src @ (P_k + a*Q_k), scatter-add into agg
__global__ __launch_bounds__(256) void k_msg(const float* __restrict__ X,
                                             const float* __restrict__ ea,
                                             const int* __restrict__ eidx) {
    __shared__ float sP[4096];
    __shared__ float sQ[4096];
    int k = blockIdx.y;
    int beg = g_off[k], end = g_off[k+1];
    if (beg == end) return;
    const float* P = g_P + k*4096;
    const float* Q = g_Q + k*4096;
    for (int i = threadIdx.x; i < 4096; i += 256) { sP[i] = P[i]; sQ[i] = Q[i]; }
    __syncthreads();
    int warp = threadIdx.x >> 5, lane = threadIdx.x & 31;
    int stride = gridDim.x * 8;
    for (int idx = beg + blockIdx.x*8 + warp; idx < end; idx += stride) {
        int e = g_eord[idx];
        float a = ea[e];
        int s  = eidx[e];
        int dn = eidx[EE + e];
        float x0 = X[s*64 + 2*lane];
        float x1 = X[s*64 + 2*lane + 1];
        float acc0 = 0.0f, acc1 = 0.0f;
        int o0 = lane, o1 = lane + 32;
        #pragma unroll
        for (int i = 0; i < 64; i += 2) {
            float xa = __shfl_sync(0xffffffff, x0, i >> 1);
            float xb = __shfl_sync(0xffffffff, x1, i >> 1);
            acc0 = fmaf(xa, fmaf(a, sQ[i*64+o0], sP[i*64+o0]), acc0);
            acc1 = fmaf(xa, fmaf(a, sQ[i*64+o1], sP[i*64+o1]), acc1);
            acc0 = fmaf(xb, fmaf(a, sQ[(i+1)*64+o0], sP[(i+1)*64+o0]), acc0);
            acc1 = fmaf(xb, fmaf(a, sQ[(i+1)*64+o1], sP[(i+1)*64+o1]), acc1);
        }
        atomicAdd(&g_agg[dn*64 + o0], acc0);
        atomicAdd(&g_agg[dn*64 + o1], acc1);
    }
}

// conv = relu(agg/deg + out@rootW + cb)
__global__ __launch_bounds__(256) void k_conv(const float* __restrict__ X,
                                              const float* __restrict__ W,
                                              const float* __restrict__ cb) {
    __shared__ float sW[64*64];
    __shared__ float sX[16*64];
    __shared__ float sB[64];
    int t = threadIdx.x;
    for (int i = t; i < 4096; i += 256) sW[i] = W[i];
    if (t < 64) sB[t] = cb[t];
    int r0 = blockIdx.x * 16;
    for (int i = t; i < 16*64; i += 256) sX[i] = X[r0*64 + i];
    __syncthreads();
    int o = t & 63;
    for (int m = (t >> 6); m < 16; m += 4) {
        int n = r0 + m;
        float dg = fmaxf(g_deg[n], 1.0f);
        float acc = sB[o] + g_agg[n*64+o] / dg;
        #pragma unroll
        for (int i = 0; i < 64; i++) acc = fmaf(sX[m*64+i], sW[i*64+o], acc);
        g_conv[n*64+o] = fmaxf(acc, 0.0f);
    }
}

__global__ void k_gru(const float* __restrict__ gi, const float* __restrict__ gh,
                      const float* __restrict__ h, float* __restrict__ out) {
    int idx = blockIdx.x*blockDim.x + threadIdx.x;
    int n = idx >> 6, d = idx & 63;
    float ir = gi[n*192+d],     iz = gi[n*192+64+d],  inn = gi[n*192+128+d];
    float hr = gh[n*192+d],     hz = gh[n*192+64+d],  hn  = gh[n*192+128+d];
    float r = sigm(ir + hr);
    float z = sigm(iz + hz);
    float nn = tanhf(inn + r * hn);
    out[idx] = (1.0f - z) * nn + z * h[idx];
}

// ------------------------- Set2Set -------------------------
__global__ __launch_bounds__(256) void k_lstm_gates(const float* __restrict__ Wih,
                                                    const float* __restrict__ Whh,
                                                    const float* __restrict__ bih,
                                                    const float* __restrict__ bhh) {
    __shared__ float sq[BB*128];
    __shared__ float sh[BB*64];
    int t = threadIdx.x;
    for (int i = t; i < BB*128; i += 256) sq[i] = g_qstar[i];
    for (int i = t; i < BB*64;  i += 256) sh[i] = g_hh[i];
    __syncthreads();
    int col = blockIdx.x*32 + (t & 31);
    int m0  = t >> 5;
    float acc[4];
    float bs = bih[col] + bhh[col];
    #pragma unroll
    for (int j = 0; j < 4; j++) acc[j] = bs;
    for (int i = 0; i < 128; i++) {
        float wv = Wih[i*256 + col];
        #pragma unroll
        for (int j = 0; j < 4; j++) acc[j] = fmaf(sq[(m0+8*j)*128 + i], wv, acc[j]);
    }
    for (int i = 0; i < 64; i++) {
        float wv = Whh[i*256 + col];
        #pragma unroll
        for (int j = 0; j < 4; j++) acc[j] = fmaf(sh[(m0+8*j)*64 + i], wv, acc[j]);
    }
    #pragma unroll
    for (int j = 0; j < 4; j++) g_gates[(m0+8*j)*256 + col] = acc[j];
}

__global__ void k_lstm_update() {
    for (int i = threadIdx.x; i < BB*64; i += blockDim.x) {
        int b = i >> 6, d = i & 63;
        float gi_ = g_gates[b*256 + d];
        float gf  = g_gates[b*256 + 64 + d];
        float gg  = g_gates[b*256 + 128 + d];
        float go  = g_gates[b*256 + 192 + d];
        float c = sigm(gf) * g_cc[i] + sigm(gi_) * tanhf(gg);
        float h = sigm(go) * tanhf(c);
        g_cc[i] = c; g_hh[i] = h; g_q[i] = h;
    }
}

__global__ __launch_bounds__(128) void k_attn(const float* __restrict__ X) {
    int b = blockIdx.x;
    int beg = g_bstart[b], end = g_bstart[b+1];
    __shared__ float red[4];
    __shared__ float sq[64];
    __shared__ float sr[128];
    int t = threadIdx.x, warp = t >> 5, lane = t & 31;
    if (t < 64) sq[t] = g_q[b*64 + t];
    __syncthreads();
    // pass 1: e[n] = dot(out[n], q[b]); track max
    float mloc = -3.4e38f;
    for (int n = beg + warp; n < end; n += 4) {
        float v = X[n*64+lane]*sq[lane] + X[n*64+32+lane]*sq[32+lane];
        #pragma unroll
        for (int off = 16; off; off >>= 1) v += __shfl_down_sync(0xffffffff, v, off);
        v = __shfl_sync(0xffffffff, v, 0);
        if (lane == 0) g_e[n] = v;
        mloc = fmaxf(mloc, v);
    }
    if (lane == 0) red[warp] = mloc;
    __syncthreads();
    float m = fmaxf(fmaxf(red[0], red[1]), fmaxf(red[2], red[3]));
    __syncthreads();
    // pass 2: den
    float dloc = 0.0f;
    for (int n = beg + t; n < end; n += 128) dloc += expf(g_e[n] - m);
    sr[t] = dloc;
    __syncthreads();
    if (t < 64) sr[t] += sr[t+64];
    __syncthreads();
    if (t < 32) sr[t] += sr[t+32];
    __syncthreads();
    if (t == 0) { float s = 0.0f; for (int i = 0; i < 32; i++) s += sr[i]; red[0] = s; }
    __syncthreads();
    float den = red[0];
    __syncthreads();
    // pass 3: r_read[d]
    int d = t & 63, half = t >> 6;
    float acc = 0.0f;
    for (int n = beg + half; n < end; n += 2) acc += expf(g_e[n] - m) * X[n*64 + d];
    sr[t] = acc;
    __syncthreads();
    if (t < 64) {
        g_qstar[b*128 + 64 + t] = (sr[t] + sr[t+64]) / den;
        g_qstar[b*128 + t]      = sq[t];
    }
}

__global__ void k_final(const float* __restrict__ W3, const float* __restrict__ b3,
                        float* __restrict__ out) {
    int b = threadIdx.x >> 5, lane = threadIdx.x & 31; // 1024 threads = 32 warps
    float v = g_y1[b*64+lane]*W3[lane] + g_y1[b*64+32+lane]*W3[32+lane];
    #pragma unroll
    for (int off = 16; off; off >>= 1) v += __shfl_down_sync(0xffffffff, v, off);
    if (lane == 0) out[b] = v + b3[0];
}

// ------------------------- host -------------------------
extern "C" void kernel_launch(void* const* d_in, const int* in_sizes, int n_in,
                              void* d_out, int out_size) {
    const float* x         = (const float*)d_in[0];
    const float* edge_attr = (const float*)d_in[1];
    const int*   edge_idx  = (const int*)  d_in[2];
    const int*   batch_map = (const int*)  d_in[3];
    const float* pre_W0 = (const float*)d_in[4];
    const float* pre_b0 = (const float*)d_in[5];
    const float* pre_W1 = (const float*)d_in[6];
    const float* pre_b1 = (const float*)d_in[7];
    const float* pre_W2 = (const float*)d_in[8];
    const float* pre_b2 = (const float*)d_in[9];
    const float* enn_W1 = (const float*)d_in[10];
    const float* enn_b1 = (const float*)d_in[11];
    const float* enn_W2 = (const float*)d_in[12];
    const float* enn_b2 = (const float*)d_in[13];
    const float* root_W = (const float*)d_in[14];
    const float* conv_b = (const float*)d_in[15];
    const float* gru_Wih = (const float*)d_in[16];
    const float* gru_Whh = (const float*)d_in[17];
    const float* gru_bih = (const float*)d_in[18];
    const float* gru_bhh = (const float*)d_in[19];
    const float* s2s_Wih = (const float*)d_in[20];
    const float* s2s_Whh = (const float*)d_in[21];
    const float* s2s_bih = (const float*)d_in[22];
    const float* s2s_bhh = (const float*)d_in[23];
    const float* post_W0 = (const float*)d_in[24];
    const float* post_b0 = (const float*)d_in[25];
    const float* post_W1 = (const float*)d_in[26];
    const float* post_b1 = (const float*)d_in[27];
    const float* post_W2 = (const float*)d_in[28];
    const float* post_b2 = (const float*)d_in[29];
    const float* post_W3 = (const float*)d_in[30];
    const float* post_b3 = (const float*)d_in[31];

    float *tmp, *bufA, *bufB, *conv, *gi, *gh, *qstar, *y1, *y2;
    cudaGetSymbolAddress((void**)&tmp,   g_tmp);
    cudaGetSymbolAddress((void**)&bufA,  g_bufA);
    cudaGetSymbolAddress((void**)&bufB,  g_bufB);
    cudaGetSymbolAddress((void**)&conv,  g_conv);
    cudaGetSymbolAddress((void**)&gi,    g_gi);
    cudaGetSymbolAddress((void**)&gh,    g_gh);
    cudaGetSymbolAddress((void**)&qstar, g_qstar);
    cudaGetSymbolAddress((void**)&y1,    g_y1);
    cudaGetSymbolAddress((void**)&y2,    g_y2);

    k_zero_init<<<16, 256>>>();
    k_deg<<<EE/256, 256>>>(edge_idx);
    k_bstart<<<1, 64>>>(batch_map);

    // pre-MLP
    k_gemm64<128, true><<<NN/16, 256>>>(x,    pre_W0, pre_b0, tmp,  NN);
    k_gemm64<64,  true><<<NN/16, 256>>>(tmp,  pre_W1, pre_b1, bufB, NN);
    k_gemm64<64,  true><<<NN/16, 256>>>(bufB, pre_W2, pre_b2, bufA, NN);

    float* cur = bufA;
    float* nxt = bufB;
    for (int l = 0; l < 3; l++) {
        k_prep<<<1, 64>>>(enn_W1 + l*64, enn_b1 + l*64);
        k_zero_agg<<<NN*DD/256, 256>>>();
        k_ke<<<EE/256, 256>>>(edge_attr);
        k_scan<<<1, 32>>>();
        k_scatter<<<EE/256, 256>>>();
        k_buildPQ<<<NK, 256>>>(enn_W2 + l*64*4096, enn_b2 + l*4096);
        k_msg<<<dim3(8, NK), 256>>>(cur, edge_attr, edge_idx);
        k_conv<<<NN/16, 256>>>(cur, root_W + l*4096, conv_b + l*64);
        k_gemm192<<<NN/16, 192>>>(conv, gru_Wih + l*64*192, gru_bih + l*192, gi);
        k_gemm192<<<NN/16, 192>>>(cur,  gru_Whh + l*64*192, gru_bhh + l*192, gh);
        k_gru<<<NN*DD/256, 256>>>(gi, gh, cur, nxt);
        float* sw = cur; cur = nxt; nxt = sw;
    }

    // Set2Set (3 steps)
    for (int s = 0; s < 3; s++) {
        k_lstm_gates<<<8, 256>>>(s2s_Wih, s2s_Whh, s2s_bih, s2s_bhh);
        k_lstm_update<<<1, 1024>>>();
        k_attn<<<BB, 128>>>(cur);
    }

    // post-MLP
    k_gemm64<128, true><<<2, 256>>>(qstar, post_W0, post_b0, y1, BB);
    k_gemm64<64,  true><<<2, 256>>>(y1,    post_W1, post_b1, y2, BB);
    k_gemm64<64,  true><<<2, 256>>>(y2,    post_W2, post_b2, y1, BB);
    k_final<<<1, 1024>>>(post_W3, post_b3, (float*)d_out);
}

// round 4
// speedup vs baseline: 1.4900x; 1.4895x over previous
#include <cuda_runtime.h>
#include <math.h>

#define NN 4096
#define DD 64
#define EE 32768
#define BB 32
#define NK 65   // intervals = 64 breakpoints + 1

// ------------------------- scratch (device globals) -------------------------
__device__ float g_bufA[NN*DD];
__device__ float g_bufB[NN*DD];
__device__ float g_agg[NN*DD];
__device__ float g_deg[NN];
__device__ float g_P[NK*4096];
__device__ float g_Q[NK*4096];
__device__ float g_w[64], g_c[64];
__device__ int   g_rank[64];
__device__ int   g_cnt[3*NK];
__device__ int   g_cur[3*NK];
__device__ int   g_ke[EE];
__device__ int   g_eord[EE];
__device__ float g_e[NN];
__device__ int   g_bstart[BB+1];

__device__ __forceinline__ float sigm(float x) { return 1.0f/(1.0f+expf(-x)); }

// ------------------------- init: zero + deg + bstart (one block) -------------------------
__global__ __launch_bounds__(1024) void k_init(const int* __restrict__ eidx,
                                               const int* __restrict__ bm) {
    int t = threadIdx.x;
    for (int i = t; i < NN; i += 1024) g_deg[i] = 0.0f;
    if (t < 3*NK) { g_cnt[t] = 0; g_cur[t] = 0; }
    __syncthreads();
    for (int e = t; e < EE; e += 1024) atomicAdd(&g_deg[eidx[EE + e]], 1.0f);
    if (t <= BB) {
        int lo = 0, hi = NN;
        while (lo < hi) { int mid = (lo+hi)>>1; if (bm[mid] < t) lo = mid+1; else hi = mid; }
        g_bstart[t] = lo;
    }
}

// ------------------------- fused 3-layer pre-MLP -------------------------
__global__ __launch_bounds__(256) void k_pre(const float* __restrict__ x,
                                             const float* __restrict__ W0, const float* __restrict__ b0,
                                             const float* __restrict__ W1, const float* __restrict__ b1,
                                             const float* __restrict__ W2, const float* __restrict__ b2,
                                             float* __restrict__ Y) {
    __shared__ float sW[8192];   // W0 (128x64); reused for W1, W2
    __shared__ float sA[2048];   // x tile (16x128); lower 1024 reused as stage-2 output
    __shared__ float sT[1024];   // stage-1 output (16x64)
    int t = threadIdx.x;
    int r0 = blockIdx.x * 16;
    for (int i = t; i < 2048; i += 256) sA[i] = x[r0*128 + i];
    for (int i = t; i < 8192; i += 256) sW[i] = W0[i];
    __syncthreads();
    int o = t & 63, mq = t >> 6;
    {
        float bv = b0[o];
        float a0 = bv, a1 = bv, a2 = bv, a3 = bv;
        #pragma unroll 4
        for (int i = 0; i < 128; i++) {
            float wv = sW[i*64 + o];
            a0 = fmaf(sA[(mq+ 0)*128 + i], wv, a0);
            a1 = fmaf(sA[(mq+ 4)*128 + i], wv, a1);
            a2 = fmaf(sA[(mq+ 8)*128 + i], wv, a2);
            a3 = fmaf(sA[(mq+12)*128 + i], wv, a3);
        }
        sT[(mq+ 0)*64+o] = fmaxf(a0, 0.0f);
        sT[(mq+ 4)*64+o] = fmaxf(a1, 0.0f);
        sT[(mq+ 8)*64+o] = fmaxf(a2, 0.0f);
        sT[(mq+12)*64+o] = fmaxf(a3, 0.0f);
    }
    __syncthreads();
    for (int i = t; i < 4096; i += 256) sW[i] = W1[i];
    __syncthreads();
    {
        float bv = b1[o];
        float a0 = bv, a1 = bv, a2 = bv, a3 = bv;
        #pragma unroll 4
        for (int i = 0; i < 64; i++) {
            float wv = sW[i*64 + o];
            a0 = fmaf(sT[(mq+ 0)*64 + i], wv, a0);
            a1 = fmaf(sT[(mq+ 4)*64 + i], wv, a1);
            a2 = fmaf(sT[(mq+ 8)*64 + i], wv, a2);
            a3 = fmaf(sT[(mq+12)*64 + i], wv, a3);
        }
        sA[(mq+ 0)*64+o] = fmaxf(a0, 0.0f);
        sA[(mq+ 4)*64+o] = fmaxf(a1, 0.0f);
        sA[(mq+ 8)*64+o] = fmaxf(a2, 0.0f);
        sA[(mq+12)*64+o] = fmaxf(a3, 0.0f);
    }
    __syncthreads();
    for (int i = t; i < 4096; i += 256) sW[i] = W2[i];
    __syncthreads();
    {
        float bv = b2[o];
        float a0 = bv, a1 = bv, a2 = bv, a3 = bv;
        #pragma unroll 4
        for (int i = 0; i < 64; i++) {
            float wv = sW[i*64 + o];
            a0 = fmaf(sA[(mq+ 0)*64 + i], wv, a0);
            a1 = fmaf(sA[(mq+ 4)*64 + i], wv, a1);
            a2 = fmaf(sA[(mq+ 8)*64 + i], wv, a2);
            a3 = fmaf(sA[(mq+12)*64 + i], wv, a3);
        }
        Y[(r0+mq+ 0)*64+o] = fmaxf(a0, 0.0f);
        Y[(r0+mq+ 4)*64+o] = fmaxf(a1, 0.0f);
        Y[(r0+mq+ 8)*64+o] = fmaxf(a2, 0.0f);
        Y[(r0+mq+12)*64+o] = fmaxf(a3, 0.0f);
    }
}

// ------------------------- prep + edge classification (fused) -------------------------
__global__ __launch_bounds__(256) void k_ke(const float* __restrict__ W1,
                                            const float* __restrict__ b1,
                                            const float* __restrict__ ea,
                                            int* __restrict__ cnt) {
    __shared__ float st[64];
    __shared__ float ss[64];   // sorted breakpoints
    int t = threadIdx.x;
    if (t < 64) {
        float w = W1[t], c = b1[t];
        float tt = (w != 0.0f) ? (-c / w) : __int_as_float(0x7f800000);
        st[t] = tt;
        if (blockIdx.x == 0) { g_w[t] = w; g_c[t] = c; }
    }
    __syncthreads();
    if (t < 64) {
        float tt = st[t];
        int r = 0;
        for (int j = 0; j < 64; j++)
            r += (st[j] < tt || (st[j] == tt && j < t)) ? 1 : 0;
        ss[r] = tt;
        if (blockIdx.x == 0) g_rank[t] = r;
    }
    __syncthreads();
    int e = blockIdx.x*256 + t;
    float a = ea[e];
    int lo = 0, hi = 64;
    while (lo < hi) { int mid = (lo+hi)>>1; if (ss[mid] < a) lo = mid+1; else hi = mid; }
    g_ke[e] = lo;
    atomicAdd(&cnt[lo], 1);
}

// ------------------------- scatter into buckets (in-block scan) -------------------------
__global__ __launch_bounds__(256) void k_scatter(const int* __restrict__ cnt,
                                                 int* __restrict__ cur) {
    __shared__ int soff[NK];
    int t = threadIdx.x;
    if (t == 0) {
        int s = 0;
        for (int k = 0; k < NK; k++) { soff[k] = s; s += cnt[k]; }
    }
    __syncthreads();
    int e = blockIdx.x*256 + t;
    int k = g_ke[e];
    int pos = soff[k] + atomicAdd(&cur[k], 1);
    g_eord[pos] = e;
}

// ------------------------- build P/Q tables (+ zero agg) -------------------------
__global__ __launch_bounds__(256) void k_buildPQ(const float* __restrict__ W2,
                                                 const float* __restrict__ b2) {
    __shared__ float sw[64], sc[64];
    __shared__ int srk[64];
    int t = threadIdx.x;
    int bid = blockIdx.y*65 + blockIdx.x;        // 0..259
    int z0 = bid*1024 + t;
    #pragma unroll
    for (int j = 0; j < 4; j++) {
        int z = z0 + j*256;
        if (z < NN*DD) g_agg[z] = 0.0f;
    }
    if (t < 64) { sw[t] = g_w[t]; sc[t] = g_c[t]; srk[t] = g_rank[t]; }
    __syncthreads();
    int k  = blockIdx.x;
    int o0 = blockIdx.y*1024 + t;
    float p[4], q[4];
    #pragma unroll
    for (int j = 0; j < 4; j++) { p[j] = b2[o0 + j*256]; q[j] = 0.0f; }
    for (int g = 0; g < 64; g++) {
        float w = sw[g], c = sc[g];
        bool act = (w > 0.0f) ? (srk[g] < k)
                 : ((w < 0.0f) ? (srk[g] >= k) : (c > 0.0f));
        if (!act) continue;
        const float* row = W2 + g*4096 + o0;
        #pragma unroll
        for (int j = 0; j < 4; j++) {
            float v = row[j*256];
            p[j] = fmaf(c, v, p[j]);
            q[j] = fmaf(w, v, q[j]);
        }
    }
    #pragma unroll
    for (int j = 0; j < 4; j++) {
        g_P[k*4096 + o0 + j*256] = p[j];
        g_Q[k*4096 + o0 + j*256] = q[j];
    }
}

// ------------------------- warp-per-edge message + scatter-add -------------------------
__global__ __launch_bounds__(256) void k_msg(const float* __restrict__ X,
                                             const float* __restrict__ ea,
                                             const int* __restrict__ eidx,
                                             const int* __restrict__ cnt) {
    __shared__ float sP[4096];
    __shared__ float sQ[4096];
    __shared__ int sbe[2];
    int t = threadIdx.x;
    int k = blockIdx.y;
    if (t == 0) {
        int s = 0;
        for (int j = 0; j < k; j++) s += cnt[j];
        sbe[0] = s; sbe[1] = s + cnt[k];
    }
    __syncthreads();
    int beg = sbe[0], end = sbe[1];
    if (beg == end) return;
    const float* P = g_P + k*4096;
    const float* Q = g_Q + k*4096;
    for (int i = t; i < 4096; i += 256) { sP[i] = P[i]; sQ[i] = Q[i]; }
    __syncthreads();
    int warp = t >> 5, lane = t & 31;
    int stride = gridDim.x * 8;
    for (int idx = beg + blockIdx.x*8 + warp; idx < end; idx += stride) {
        int e = g_eord[idx];
        float a = ea[e];
        int s  = eidx[e];
        int dn = eidx[EE + e];
        float x0 = X[s*64 + 2*lane];
        float x1 = X[s*64 + 2*lane + 1];
        float acc0 = 0.0f, acc1 = 0.0f;
        int o0 = lane, o1 = lane + 32;
        #pragma unroll
        for (int i = 0; i < 64; i += 2) {
            float xa = __shfl_sync(0xffffffff, x0, i >> 1);
            float xb = __shfl_sync(0xffffffff, x1, i >> 1);
            acc0 = fmaf(xa, fmaf(a, sQ[i*64+o0], sP[i*64+o0]), acc0);
            acc1 = fmaf(xa, fmaf(a, sQ[i*64+o1], sP[i*64+o1]), acc1);
            acc0 = fmaf(xb, fmaf(a, sQ[(i+1)*64+o0], sP[(i+1)*64+o0]), acc0);
            acc1 = fmaf(xb, fmaf(a, sQ[(i+1)*64+o1], sP[(i+1)*64+o1]), acc1);
        }
        atomicAdd(&g_agg[dn*64 + o0], acc0);
        atomicAdd(&g_agg[dn*64 + o1], acc1);
    }
}

// ------------------------- fused conv + GRU -------------------------
__global__ __launch_bounds__(256) void k_convgru(const float* __restrict__ X,
                                                 const float* __restrict__ rootW,
                                                 const float* __restrict__ cb,
                                                 const float* __restrict__ Wih,
                                                 const float* __restrict__ bih,
                                                 const float* __restrict__ Whh,
                                                 const float* __restrict__ bhh,
                                                 float* __restrict__ Y) {
    __shared__ float sH[1024];
    __shared__ float sConv[1024];
    __shared__ float sBig[6144];  // phase1: rootW(4096); phase2/3: gi(0..3071)+gh(3072..6143)
    int t = threadIdx.x;
    int r0 = blockIdx.x * 16;
    for (int i = t; i < 1024; i += 256) sH[i] = X[r0*64 + i];
    for (int i = t; i < 4096; i += 256) sBig[i] = rootW[i];
    __syncthreads();
    int o = t & 63, mq = t >> 6;
    {
        float bv = cb[o];
        int n0 = r0 + mq;
        float a0 = fmaf(g_agg[(n0+ 0)*64+o], 1.0f/fmaxf(g_deg[n0+ 0], 1.0f), bv);
        float a1 = fmaf(g_agg[(n0+ 4)*64+o], 1.0f/fmaxf(g_deg[n0+ 4], 1.0f), bv);
        float a2 = fmaf(g_agg[(n0+ 8)*64+o], 1.0f/fmaxf(g_deg[n0+ 8], 1.0f), bv);
        float a3 = fmaf(g_agg[(n0+12)*64+o], 1.0f/fmaxf(g_deg[n0+12], 1.0f), bv);
        #pragma unroll 4
        for (int i = 0; i < 64; i++) {
            float wv = sBig[i*64 + o];
            a0 = fmaf(sH[(mq+ 0)*64 + i], wv, a0);
            a1 = fmaf(sH[(mq+ 4)*64 + i], wv, a1);
            a2 = fmaf(sH[(mq+ 8)*64 + i], wv, a2);
            a3 = fmaf(sH[(mq+12)*64 + i], wv, a3);
        }
        sConv[(mq+ 0)*64+o] = fmaxf(a0, 0.0f);
        sConv[(mq+ 4)*64+o] = fmaxf(a1, 0.0f);
        sConv[(mq+ 8)*64+o] = fmaxf(a2, 0.0f);
        sConv[(mq+12)*64+o] = fmaxf(a3, 0.0f);
    }
    __syncthreads();
    if (t < 192) {
        float gi[16], gh[16];
        float bi = bih[t], bh = bhh[t];
        #pragma unroll
        for (int m = 0; m < 16; m++) { gi[m] = bi; gh[m] = bh; }
        #pragma unroll 4
        for (int kk = 0; kk < 64; kk++) {
            float wi = Wih[kk*192 + t];
            float wh = Whh[kk*192 + t];
            #pragma unroll
            for (int m = 0; m < 16; m++) {
                gi[m] = fmaf(sConv[m*64 + kk], wi, gi[m]);
                gh[m] = fmaf(sH[m*64 + kk],    wh, gh[m]);
            }
        }
        #pragma unroll
        for (int m = 0; m < 16; m++) {
            sBig[m*192 + t]        = gi[m];
            sBig[3072 + m*192 + t] = gh[m];
        }
    }
    __syncthreads();
    #pragma unroll
    for (int j = 0; j < 4; j++) {
        int idx = t + j*256;
        int m = idx >> 6, d = idx & 63;
        float ir = sBig[m*192+d],      iz = sBig[m*192+64+d],      inn = sBig[m*192+128+d];
        float hr = sBig[3072+m*192+d], hz = sBig[3072+m*192+64+d], hn  = sBig[3072+m*192+128+d];
        float r = sigm(ir + hr);
        float z = sigm(iz + hz);
        float nv = tanhf(inn + r * hn);
        float h = sH[m*64 + d];
        Y[(r0+m)*64 + d] = (1.0f - z) * nv + z * h;
    }
}

// ------------------------- fused Set2Set (3 steps) + post-MLP + final -------------------------
__global__ __launch_bounds__(256) void k_s2s(const float* __restrict__ X,
                                             const float* __restrict__ Wih,
                                             const float* __restrict__ Whh,
                                             const float* __restrict__ bih,
                                             const float* __restrict__ bhh,
                                             const float* __restrict__ pW0, const float* __restrict__ pb0,
                                             const float* __restrict__ pW1, const float* __restrict__ pb1,
                                             const float* __restrict__ pW2, const float* __restrict__ pb2,
                                             const float* __restrict__ pW3, const float* __restrict__ pb3,
                                             float* __restrict__ out) {
    __shared__ float sqs[128];
    __shared__ float shh[64], scc[64];
    __shared__ float sg[256];
    __shared__ float sred[256];
    __shared__ float smax, sden;
    __shared__ float sy[64], sy2[64];
    int b = blockIdx.x;
    int t = threadIdx.x;
    int beg = g_bstart[b], end = g_bstart[b+1];
    if (t < 128) sqs[t] = 0.0f;
    if (t < 64) { shh[t] = 0.0f; scc[t] = 0.0f; }
    __syncthreads();
    for (int step = 0; step < 3; step++) {
        // gates: col t of q_star@Wih + hh@Whh + biases
        float acc0 = bih[t] + bhh[t], acc1 = 0.0f;
        #pragma unroll 8
        for (int i = 0; i < 128; i += 2) {
            acc0 = fmaf(sqs[i],   Wih[i*256 + t],     acc0);
            acc1 = fmaf(sqs[i+1], Wih[(i+1)*256 + t], acc1);
        }
        #pragma unroll 8
        for (int i = 0; i < 64; i += 2) {
            acc0 = fmaf(shh[i],   Whh[i*256 + t],     acc0);
            acc1 = fmaf(shh[i+1], Whh[(i+1)*256 + t], acc1);
        }
        sg[t] = acc0 + acc1;
        __syncthreads();
        // LSTM update
        if (t < 64) {
            float c = sigm(sg[64+t]) * scc[t] + sigm(sg[t]) * tanhf(sg[128+t]);
            float h = sigm(sg[192+t]) * tanhf(c);
            scc[t] = c; shh[t] = h;
        }
        __syncthreads();
        // attention pass1: e[n] + max
        int warp = t >> 5, lane = t & 31;
        float mloc = -3.4e38f;
        for (int n = beg + warp; n < end; n += 8) {
            float v = X[n*64 + lane]*shh[lane] + X[n*64 + 32 + lane]*shh[32 + lane];
            #pragma unroll
            for (int off = 16; off; off >>= 1) v += __shfl_down_sync(0xffffffffu, v, off);
            v = __shfl_sync(0xffffffffu, v, 0);
            if (lane == 0) g_e[n] = v;
            mloc = fmaxf(mloc, v);
        }
        if (lane == 0) sred[warp] = mloc;
        __syncthreads();
        if (t == 0) {
            float m = sred[0];
            for (int j = 1; j < 8; j++) m = fmaxf(m, sred[j]);
            smax = m;
        }
        __syncthreads();
        float m = smax;
        // pass2: denominator
        float dl = 0.0f;
        for (int n = beg + t; n < end; n += 256) dl += expf(g_e[n] - m);
        sred[t] = dl;
        __syncthreads();
        if (t < 128) sred[t] += sred[t+128];
        __syncthreads();
        if (t < 64) sred[t] += sred[t+64];
        __syncthreads();
        if (t == 0) { float s = 0.0f; for (int j = 0; j < 64; j++) s += sred[j]; sden = s; }
        __syncthreads();
        float den = sden;
        // pass3: r_read
        int d = t & 63, quarter = t >> 6;
        float ra = 0.0f;
        for (int n = beg + quarter; n < end; n += 4) ra += expf(g_e[n] - m) * X[n*64 + d];
        __syncthreads();
        sred[t] = ra;
        __syncthreads();
        if (t < 64) {
            sqs[64 + t] = (sred[t] + sred[t+64] + sred[t+128] + sred[t+192]) / den;
            sqs[t]      = shh[t];
        }
        __syncthreads();
    }
    // post-MLP + final
    if (t < 64) {
        float acc = pb0[t];
        #pragma unroll 8
        for (int i = 0; i < 128; i++) acc = fmaf(sqs[i], pW0[i*64 + t], acc);
        sy[t] = fmaxf(acc, 0.0f);
    }
    __syncthreads();
    if (t < 64) {
        float acc = pb1[t];
        #pragma unroll 8
        for (int i = 0; i < 64; i++) acc = fmaf(sy[i], pW1[i*64 + t], acc);
        sy2[t] = fmaxf(acc, 0.0f);
    }
    __syncthreads();
    if (t < 64) {
        float acc = pb2[t];
        #pragma unroll 8
        for (int i = 0; i < 64; i++) acc = fmaf(sy2[i], pW2[i*64 + t], acc);
        sy[t] = fmaxf(acc, 0.0f);
    }
    __syncthreads();
    if (t < 32) {
        float v = sy[t]*pW3[t] + sy[t+32]*pW3[t+32];
        #pragma unroll
        for (int off = 16; off; off >>= 1) v += __shfl_down_sync(0xffffffffu, v, off);
        if (t == 0) out[b] = v + pb3[0];
    }
}

// ------------------------- host -------------------------
extern "C" void kernel_launch(void* const* d_in, const int* in_sizes, int n_in,
                              void* d_out, int out_size) {
    const float* x         = (const float*)d_in[0];
    const float* edge_attr = (const float*)d_in[1];
    const int*   edge_idx  = (const int*)  d_in[2];
    const int*   batch_map = (const int*)  d_in[3];
    const float* pre_W0 = (const float*)d_in[4];
    const float* pre_b0 = (const float*)d_in[5];
    const float* pre_W1 = (const float*)d_in[6];
    const float* pre_b1 = (const float*)d_in[7];
    const float* pre_W2 = (const float*)d_in[8];
    const float* pre_b2 = (const float*)d_in[9];
    const float* enn_W1 = (const float*)d_in[10];
    const float* enn_b1 = (const float*)d_in[11];
    const float* enn_W2 = (const float*)d_in[12];
    const float* enn_b2 = (const float*)d_in[13];
    const float* root_W = (const float*)d_in[14];
    const float* conv_b = (const float*)d_in[15];
    const float* gru_Wih = (const float*)d_in[16];
    const float* gru_Whh = (const float*)d_in[17];
    const float* gru_bih = (const float*)d_in[18];
    const float* gru_bhh = (const float*)d_in[19];
    const float* s2s_Wih = (const float*)d_in[20];
    const float* s2s_Whh = (const float*)d_in[21];
    const float* s2s_bih = (const float*)d_in[22];
    const float* s2s_bhh = (const float*)d_in[23];
    const float* post_W0 = (const float*)d_in[24];
    const float* post_b0 = (const float*)d_in[25];
    const float* post_W1 = (const float*)d_in[26];
    const float* post_b1 = (const float*)d_in[27];
    const float* post_W2 = (const float*)d_in[28];
    const float* post_b2 = (const float*)d_in[29];
    const float* post_W3 = (const float*)d_in[30];
    const float* post_b3 = (const float*)d_in[31];

    float *bufA, *bufB;
    int *cnt, *cur;
    cudaGetSymbolAddress((void**)&bufA, g_bufA);
    cudaGetSymbolAddress((void**)&bufB, g_bufB);
    cudaGetSymbolAddress((void**)&cnt,  g_cnt);
    cudaGetSymbolAddress((void**)&cur,  g_cur);

    k_init<<<1, 1024>>>(edge_idx, batch_map);
    k_pre<<<NN/16, 256>>>(x, pre_W0, pre_b0, pre_W1, pre_b1, pre_W2, pre_b2, bufA);

    float* curbuf = bufA;
    float* nxtbuf = bufB;
    for (int l = 0; l < 3; l++) {
        int* cnt_l = cnt + l*NK;
        int* cur_l = cur + l*NK;
        k_ke<<<EE/256, 256>>>(enn_W1 + l*64, enn_b1 + l*64, edge_attr, cnt_l);
        k_scatter<<<EE/256, 256>>>(cnt_l, cur_l);
        k_buildPQ<<<dim3(65, 4), 256>>>(enn_W2 + l*64*4096, enn_b2 + l*4096);
        k_msg<<<dim3(16, NK), 256>>>(curbuf, edge_attr, edge_idx, cnt_l);
        k_convgru<<<NN/16, 256>>>(curbuf, root_W + l*4096, conv_b + l*64,
                                  gru_Wih + l*64*192, gru_bih + l*192,
                                  gru_Whh + l*64*192, gru_bhh + l*192, nxtbuf);
        float* sw = curbuf; curbuf = nxtbuf; nxtbuf = sw;
    }

    k_s2s<<<BB, 256>>>(curbuf, s2s_Wih, s2s_Whh, s2s_bih, s2s_bhh,
                       post_W0, post_b0, post_W1, post_b1,
                       post_W2, post_b2, post_W3, post_b3, (float*)d_out);
}

// round 5
// speedup vs baseline: 1.5281x; 1.0255x over previous
#include <cuda_runtime.h>
#include <math.h>

#define NN 4096
#define DD 64
#define EE 32768
#define BB 32
#define NK 65   // intervals = 64 breakpoints + 1

// ------------------------- scratch (device globals) -------------------------
__device__ float  g_bufA[NN*DD];
__device__ float  g_bufB[NN*DD];
__device__ float  g_agg[NN*DD];
__device__ float  g_deg[NN];
__device__ float  g_P[3*NK*4096];
__device__ float  g_Q[3*NK*4096];
__device__ float  g_w[3*64], g_c[3*64];
__device__ int    g_rank[3*64];
__device__ int    g_ke[3*EE];
__device__ float4 g_edata[3*EE];
__device__ int    g_bhist[3*NK*128];
__device__ int    g_bbase[3*NK*128];
__device__ int    g_off[3*(NK+1)];
__device__ float  g_e[NN];
__device__ int    g_bstart[BB+1];

__device__ __forceinline__ float sigm(float x) { return 1.0f/(1.0f+expf(-x)); }

// packed f32x2 helpers
__device__ __forceinline__ unsigned long long pk2(float lo, float hi) {
    unsigned long long r;
    asm("mov.b64 %0, {%1, %2};" : "=l"(r) : "f"(lo), "f"(hi));
    return r;
}
__device__ __forceinline__ unsigned long long fma2(unsigned long long a,
                                                   unsigned long long b,
                                                   unsigned long long c) {
    unsigned long long d;
    asm("fma.rn.f32x2 %0, %1, %2, %3;" : "=l"(d) : "l"(a), "l"(b), "l"(c));
    return d;
}
__device__ __forceinline__ void upk2(unsigned long long v, float& lo, float& hi) {
    asm("mov.b64 {%0, %1}, %2;" : "=f"(lo), "=f"(hi) : "l"(v));
}

// ------------------------- edge classification: all 3 layers + deg -------------------------
__global__ __launch_bounds__(256) void k_ke3(const float* __restrict__ W1,
                                             const float* __restrict__ b1,
                                             const float* __restrict__ ea,
                                             const int* __restrict__ eidx) {
    __shared__ float st[64];   // raw breakpoints
    __shared__ float ss[64];   // sorted breakpoints
    __shared__ int   hist[NK];
    int t = threadIdx.x, b = blockIdx.x;
    int e = b*256 + t;
    float a = ea[e];
    atomicAdd(&g_deg[eidx[EE + e]], 1.0f);
    for (int l = 0; l < 3; l++) {
        if (t < NK) hist[t] = 0;
        if (t < 64) {
            float w = W1[l*64 + t], c = b1[l*64 + t];
            float tt = (w != 0.0f) ? (-c / w) : __int_as_float(0x7f800000);
            st[t] = tt;
            if (b == 0) { g_w[l*64 + t] = w; g_c[l*64 + t] = c; }
        }
        __syncthreads();
        if (t < 64) {
            float tt = st[t];
            int r = 0;
            for (int j = 0; j < 64; j++)
                r += (st[j] < tt || (st[j] == tt && j < t)) ? 1 : 0;
            ss[r] = tt;
            if (b == 0) g_rank[l*64 + t] = r;
        }
        __syncthreads();
        int lo = 0, hi = 64;
        while (lo < hi) { int mid = (lo+hi)>>1; if (ss[mid] < a) lo = mid+1; else hi = mid; }
        g_ke[l*EE + e] = lo;
        atomicAdd(&hist[lo], 1);
        __syncthreads();
        if (t < NK) g_bhist[(l*NK + t)*128 + b] = hist[t];
        __syncthreads();
    }
}

// ------------------------- offsets: per-block bases + bucket offsets + bstart -------------------------
__global__ __launch_bounds__(256) void k_offsets(const int* __restrict__ bm) {
    __shared__ int stot[3*NK];
    int t = threadIdx.x, lane = t & 31, warp = t >> 5;
    for (int lk = warp; lk < 3*NK; lk += 8) {
        int4 v = ((const int4*)(g_bhist + lk*128))[lane];
        int p1 = v.x + v.y;
        int p2 = p1 + v.z;
        int tot = p2 + v.w;
        int inc = tot;
        #pragma unroll
        for (int off = 1; off < 32; off <<= 1) {
            int n = __shfl_up_sync(0xffffffffu, inc, off);
            if (lane >= off) inc += n;
        }
        int excl = inc - tot;
        int4 o;
        o.x = excl; o.y = excl + v.x; o.z = excl + p1; o.w = excl + p2;
        ((int4*)(g_bbase + lk*128))[lane] = o;
        if (lane == 31) stot[lk] = inc;
    }
    __syncthreads();
    if (t < 3) {
        int s = 0;
        for (int k = 0; k < NK; k++) { g_off[t*(NK+1) + k] = s; s += stot[t*NK + k]; }
        g_off[t*(NK+1) + NK] = s;
    }
    if (t >= 128 && t <= 128 + BB) {
        int bb = t - 128;
        int lo = 0, hi = NN;
        while (lo < hi) { int mid = (lo+hi)>>1; if (bm[mid] < bb) lo = mid+1; else hi = mid; }
        g_bstart[bb] = lo;
    }
}

// ------------------------- scatter: deterministic, no global atomics -------------------------
__global__ __launch_bounds__(256) void k_scatter3(const float* __restrict__ ea,
                                                  const int* __restrict__ eidx) {
    __shared__ int sbase[NK];
    __shared__ int scnt[NK];
    int t = threadIdx.x, b = blockIdx.x;
    int e = b*256 + t;
    float a = ea[e];
    int s = eidx[e], d = eidx[EE + e];
    float4 rec;
    rec.x = __int_as_float(s);
    rec.y = __int_as_float(d);
    rec.z = a;
    rec.w = 0.0f;
    for (int l = 0; l < 3; l++) {
        if (t < NK) {
            sbase[t] = g_off[l*(NK+1) + t] + g_bbase[(l*NK + t)*128 + b];
            scnt[t] = 0;
        }
        __syncthreads();
        int k = g_ke[l*EE + e];
        int pos = sbase[k] + atomicAdd(&scnt[k], 1);
        g_edata[l*EE + pos] = rec;
        __syncthreads();
    }
}

// ------------------------- build P/Q tables, all 3 layers -------------------------
__global__ __launch_bounds__(256) void k_buildPQ3(const float* __restrict__ W2,
                                                  const float* __restrict__ b2) {
    __shared__ float sw[64], sc[64];
    __shared__ int srk[64];
    int t = threadIdx.x;
    int l = blockIdx.z;
    if (t < 64) { sw[t] = g_w[l*64+t]; sc[t] = g_c[l*64+t]; srk[t] = g_rank[l*64+t]; }
    __syncthreads();
    int k  = blockIdx.x;
    int o0 = blockIdx.y*1024 + t;
    const float* W2l = W2 + l*64*4096;
    const float* b2l = b2 + l*4096;
    float p[4], q[4];
    #pragma unroll
    for (int j = 0; j < 4; j++) { p[j] = b2l[o0 + j*256]; q[j] = 0.0f; }
    for (int g = 0; g < 64; g++) {
        float w = sw[g], c = sc[g];
        bool act = (w > 0.0f) ? (srk[g] < k)
                 : ((w < 0.0f) ? (srk[g] >= k) : (c > 0.0f));
        if (!act) continue;
        const float* row = W2l + g*4096 + o0;
        #pragma unroll
        for (int j = 0; j < 4; j++) {
            float v = row[j*256];
            p[j] = fmaf(c, v, p[j]);
            q[j] = fmaf(w, v, q[j]);
        }
    }
    int base = (l*NK + k)*4096 + o0;
    #pragma unroll
    for (int j = 0; j < 4; j++) {
        g_P[base + j*256] = p[j];
        g_Q[base + j*256] = q[j];
    }
}

// ------------------------- fused 3-layer pre-MLP -------------------------
__global__ __launch_bounds__(256) void k_pre(const float* __restrict__ x,
                                             const float* __restrict__ W0, const float* __restrict__ b0,
                                             const float* __restrict__ W1, const float* __restrict__ b1,
                                             const float* __restrict__ W2, const float* __restrict__ b2,
                                             float* __restrict__ Y) {
    __shared__ float sW[8192];
    __shared__ float sA[2048];
    __shared__ float sT[1024];
    int t = threadIdx.x;
    int r0 = blockIdx.x * 16;
    for (int i = t; i < 2048; i += 256) sA[i] = x[r0*128 + i];
    for (int i = t; i < 8192; i += 256) sW[i] = W0[i];
    __syncthreads();
    int o = t & 63, mq = t >> 6;
    {
        float bv = b0[o];
        float a0 = bv, a1 = bv, a2 = bv, a3 = bv;
        #pragma unroll 4
        for (int i = 0; i < 128; i++) {
            float wv = sW[i*64 + o];
            a0 = fmaf(sA[(mq+ 0)*128 + i], wv, a0);
            a1 = fmaf(sA[(mq+ 4)*128 + i], wv, a1);
            a2 = fmaf(sA[(mq+ 8)*128 + i], wv, a2);
            a3 = fmaf(sA[(mq+12)*128 + i], wv, a3);
        }
        sT[(mq+ 0)*64+o] = fmaxf(a0, 0.0f);
        sT[(mq+ 4)*64+o] = fmaxf(a1, 0.0f);
        sT[(mq+ 8)*64+o] = fmaxf(a2, 0.0f);
        sT[(mq+12)*64+o] = fmaxf(a3, 0.0f);
    }
    __syncthreads();
    for (int i = t; i < 4096; i += 256) sW[i] = W1[i];
    __syncthreads();
    {
        float bv = b1[o];
        float a0 = bv, a1 = bv, a2 = bv, a3 = bv;
        #pragma unroll 4
        for (int i = 0; i < 64; i++) {
            float wv = sW[i*64 + o];
            a0 = fmaf(sT[(mq+ 0)*64 + i], wv, a0);
            a1 = fmaf(sT[(mq+ 4)*64 + i], wv, a1);
            a2 = fmaf(sT[(mq+ 8)*64 + i], wv, a2);
            a3 = fmaf(sT[(mq+12)*64 + i], wv, a3);
        }
        sA[(mq+ 0)*64+o] = fmaxf(a0, 0.0f);
        sA[(mq+ 4)*64+o] = fmaxf(a1, 0.0f);
        sA[(mq+ 8)*64+o] = fmaxf(a2, 0.0f);
        sA[(mq+12)*64+o] = fmaxf(a3, 0.0f);
    }
    __syncthreads();
    for (int i = t; i < 4096; i += 256) sW[i] = W2[i];
    __syncthreads();
    {
        float bv = b2[o];
        float a0 = bv, a1 = bv, a2 = bv, a3 = bv;
        #pragma unroll 4
        for (int i = 0; i < 64; i++) {
            float wv = sW[i*64 + o];
            a0 = fmaf(sA[(mq+ 0)*64 + i], wv, a0);
            a1 = fmaf(sA[(mq+ 4)*64 + i], wv, a1);
            a2 = fmaf(sA[(mq+ 8)*64 + i], wv, a2);
            a3 = fmaf(sA[(mq+12)*64 + i], wv, a3);
        }
        Y[(r0+mq+ 0)*64+o] = fmaxf(a0, 0.0f);
        Y[(r0+mq+ 4)*64+o] = fmaxf(a1, 0.0f);
        Y[(r0+mq+ 8)*64+o] = fmaxf(a2, 0.0f);
        Y[(r0+mq+12)*64+o] = fmaxf(a3, 0.0f);
    }
}

// ------------------------- warp-per-edge message (f32x2 packed) -------------------------
__global__ __launch_bounds__(256) void k_msg(const float* __restrict__ X, int l) {
    // paired layout: element (row i, lane o) pairs outputs (o, o+32) adjacently
    __shared__ float sP2[4096];
    __shared__ float sQ2[4096];
    int t = threadIdx.x;
    int k = blockIdx.y;
    int beg = g_off[l*(NK+1) + k];
    int end = g_off[l*(NK+1) + k + 1];
    if (beg == end) return;
    const float* P = g_P + (l*NK + k)*4096;
    const float* Q = g_Q + (l*NK + k)*4096;
    for (int i = t; i < 4096; i += 256) {
        int row = i >> 6, col = i & 63;
        int o = col & 31, half = col >> 5;
        int dstidx = (row*32 + o)*2 + half;
        sP2[dstidx] = P[i];
        sQ2[dstidx] = Q[i];
    }
    __syncthreads();
    int warp = t >> 5, lane = t & 31;
    int stride = gridDim.x * 8;
    const float2* X2 = (const float2*)X;
    for (int idx = beg + blockIdx.x*8 + warp; idx < end; idx += stride) {
        float4 rec = g_edata[l*EE + idx];
        int s  = __float_as_int(rec.x);
        int dn = __float_as_int(rec.y);
        float a = rec.z;
        unsigned long long apack = pk2(a, a);
        float2 xv = X2[s*32 + lane];
        unsigned long long acc = pk2(0.0f, 0.0f);
        #pragma unroll
        for (int i = 0; i < 64; i += 2) {
            float xa = __shfl_sync(0xffffffffu, xv.x, i >> 1);
            float xb = __shfl_sync(0xffffffffu, xv.y, i >> 1);
            {
                const float2* pp = (const float2*)&sP2[(i*32 + lane)*2];
                const float2* qq = (const float2*)&sQ2[(i*32 + lane)*2];
                float2 p = *pp, q = *qq;
                unsigned long long m = fma2(apack, pk2(q.x, q.y), pk2(p.x, p.y));
                acc = fma2(pk2(xa, xa), m, acc);
            }
            {
                const float2* pp = (const float2*)&sP2[((i+1)*32 + lane)*2];
                const float2* qq = (const float2*)&sQ2[((i+1)*32 + lane)*2];
                float2 p = *pp, q = *qq;
                unsigned long long m = fma2(apack, pk2(q.x, q.y), pk2(p.x, p.y));
                acc = fma2(pk2(xb, xb), m, acc);
            }
        }
        float acc0, acc1;
        upk2(acc, acc0, acc1);
        atomicAdd(&g_agg[dn*64 + lane],      acc0);
        atomicAdd(&g_agg[dn*64 + lane + 32], acc1);
    }
}

// ------------------------- fused conv + GRU (self-cleans g_agg) -------------------------
__global__ __launch_bounds__(256) void k_convgru(const float* __restrict__ X,
                                                 const float* __restrict__ rootW,
                                                 const float* __restrict__ cb,
                                                 const float* __restrict__ Wih,
                                                 const float* __restrict__ bih,
                                                 const float* __restrict__ Whh,
                                                 const float* __restrict__ bhh,
                                                 float* __restrict__ Y) {
    __shared__ float sH[1024];
    __shared__ float sConv[1024];
    __shared__ float sBig[6144];
    int t = threadIdx.x;
    int r0 = blockIdx.x * 16;
    for (int i = t; i < 1024; i += 256) sH[i] = X[r0*64 + i];
    for (int i = t; i < 4096; i += 256) sBig[i] = rootW[i];
    __syncthreads();
    int o = t & 63, mq = t >> 6;
    {
        float bv = cb[o];
        int n0 = r0 + mq;
        float a0 = fmaf(g_agg[(n0+ 0)*64+o], 1.0f/fmaxf(g_deg[n0+ 0], 1.0f), bv);
        float a1 = fmaf(g_agg[(n0+ 4)*64+o], 1.0f/fmaxf(g_deg[n0+ 4], 1.0f), bv);
        float a2 = fmaf(g_agg[(n0+ 8)*64+o], 1.0f/fmaxf(g_deg[n0+ 8], 1.0f), bv);
        float a3 = fmaf(g_agg[(n0+12)*64+o], 1.0f/fmaxf(g_deg[n0+12], 1.0f), bv);
        // self-clean agg for the next layer
        g_agg[(n0+ 0)*64+o] = 0.0f;
        g_agg[(n0+ 4)*64+o] = 0.0f;
        g_agg[(n0+ 8)*64+o] = 0.0f;
        g_agg[(n0+12)*64+o] = 0.0f;
        #pragma unroll 4
        for (int i = 0; i < 64; i++) {
            float wv = sBig[i*64 + o];
            a0 = fmaf(sH[(mq+ 0)*64 + i], wv, a0);
            a1 = fmaf(sH[(mq+ 4)*64 + i], wv, a1);
            a2 = fmaf(sH[(mq+ 8)*64 + i], wv, a2);
            a3 = fmaf(sH[(mq+12)*64 + i], wv, a3);
        }
        sConv[(mq+ 0)*64+o] = fmaxf(a0, 0.0f);
        sConv[(mq+ 4)*64+o] = fmaxf(a1, 0.0f);
        sConv[(mq+ 8)*64+o] = fmaxf(a2, 0.0f);
        sConv[(mq+12)*64+o] = fmaxf(a3, 0.0f);
    }
    __syncthreads();
    if (t < 192) {
        float gi[16], gh[16];
        float bi = bih[t], bh = bhh[t];
        #pragma unroll
        for (int m = 0; m < 16; m++) { gi[m] = bi; gh[m] = bh; }
        #pragma unroll 4
        for (int kk = 0; kk < 64; kk++) {
            float wi = Wih[kk*192 + t];
            float wh = Whh[kk*192 + t];
            #pragma unroll
            for (int m = 0; m < 16; m++) {
                gi[m] = fmaf(sConv[m*64 + kk], wi, gi[m]);
                gh[m] = fmaf(sH[m*64 + kk],    wh, gh[m]);
            }
        }
        #pragma unroll
        for (int m = 0; m < 16; m++) {
            sBig[m*192 + t]        = gi[m];
            sBig[3072 + m*192 + t] = gh[m];
        }
    }
    __syncthreads();
    #pragma unroll
    for (int j = 0; j < 4; j++) {
        int idx = t + j*256;
        int m = idx >> 6, d = idx & 63;
        float ir = sBig[m*192+d],      iz = sBig[m*192+64+d],      inn = sBig[m*192+128+d];
        float hr = sBig[3072+m*192+d], hz = sBig[3072+m*192+64+d], hn  = sBig[3072+m*192+128+d];
        float r = sigm(ir + hr);
        float z = sigm(iz + hz);
        float nv = tanhf(inn + r * hn);
        float h = sH[m*64 + d];
        Y[(r0+m)*64 + d] = (1.0f - z) * nv + z * h;
    }
}

// ------------------------- fused Set2Set (3 steps) + post-MLP + final -------------------------
__global__ __launch_bounds__(256) void k_s2s(const float* __restrict__ X,
                                             const float* __restrict__ Wih,
                                             const float* __restrict__ Whh,
                                             const float* __restrict__ bih,
                                             const float* __restrict__ bhh,
                                             const float* __restrict__ pW0, const float* __restrict__ pb0,
                                             const float* __restrict__ pW1, const float* __restrict__ pb1,
                                             const float* __restrict__ pW2, const float* __restrict__ pb2,
                                             const float* __restrict__ pW3, const float* __restrict__ pb3,
                                             float* __restrict__ out) {
    __shared__ float sqs[128];
    __shared__ float shh[64], scc[64];
    __shared__ float sg[256];
    __shared__ float sred[256];
    __shared__ float smax, sden;
    __shared__ float sy[64], sy2[64];
    int b = blockIdx.x;
    int t = threadIdx.x;
    int beg = g_bstart[b], end = g_bstart[b+1];
    if (t < 128) sqs[t] = 0.0f;
    if (t < 64) { shh[t] = 0.0f; scc[t] = 0.0f; }
    __syncthreads();
    for (int step = 0; step < 3; step++) {
        float acc0 = bih[t] + bhh[t], acc1 = 0.0f;
        #pragma unroll 8
        for (int i = 0; i < 128; i += 2) {
            acc0 = fmaf(sqs[i],   Wih[i*256 + t],     acc0);
            acc1 = fmaf(sqs[i+1], Wih[(i+1)*256 + t], acc1);
        }
        #pragma unroll 8
        for (int i = 0; i < 64; i += 2) {
            acc0 = fmaf(shh[i],   Whh[i*256 + t],     acc0);
            acc1 = fmaf(shh[i+1], Whh[(i+1)*256 + t], acc1);
        }
        sg[t] = acc0 + acc1;
        __syncthreads();
        if (t < 64) {
            float c = sigm(sg[64+t]) * scc[t] + sigm(sg[t]) * tanhf(sg[128+t]);
            float h = sigm(sg[192+t]) * tanhf(c);
            scc[t] = c; shh[t] = h;
        }
        __syncthreads();
        int warp = t >> 5, lane = t & 31;
        float mloc = -3.4e38f;
        for (int n = beg + warp; n < end; n += 8) {
            float v = X[n*64 + lane]*shh[lane] + X[n*64 + 32 + lane]*shh[32 + lane];
            #pragma unroll
            for (int off = 16; off; off >>= 1) v += __shfl_down_sync(0xffffffffu, v, off);
            v = __shfl_sync(0xffffffffu, v, 0);
            if (lane == 0) g_e[n] = v;
            mloc = fmaxf(mloc, v);
        }
        if (lane == 0) sred[warp] = mloc;
        __syncthreads();
        if (t == 0) {
            float m = sred[0];
            for (int j = 1; j < 8; j++) m = fmaxf(m, sred[j]);
            smax = m;
        }
        __syncthreads();
        float m = smax;
        float dl = 0.0f;
        for (int n = beg + t; n < end; n += 256) dl += expf(g_e[n] - m);
        sred[t] = dl;
        __syncthreads();
        if (t < 128) sred[t] += sred[t+128];
        __syncthreads();
        if (t < 64) sred[t] += sred[t+64];
        __syncthreads();
        if (t == 0) { float s = 0.0f; for (int j = 0; j < 64; j++) s += sred[j]; sden = s; }
        __syncthreads();
        float den = sden;
        int d = t & 63, quarter = t >> 6;
        float ra = 0.0f;
        for (int n = beg + quarter; n < end; n += 4) ra += expf(g_e[n] - m) * X[n*64 + d];
        __syncthreads();
        sred[t] = ra;
        __syncthreads();
        if (t < 64) {
            sqs[64 + t] = (sred[t] + sred[t+64] + sred[t+128] + sred[t+192]) / den;
            sqs[t]      = shh[t];
        }
        __syncthreads();
    }
    if (t < 64) {
        float acc = pb0[t];
        #pragma unroll 8
        for (int i = 0; i < 128; i++) acc = fmaf(sqs[i], pW0[i*64 + t], acc);
        sy[t] = fmaxf(acc, 0.0f);
    }
    __syncthreads();
    if (t < 64) {
        float acc = pb1[t];
        #pragma unroll 8
        for (int i = 0; i < 64; i++) acc = fmaf(sy[i], pW1[i*64 + t], acc);
        sy2[t] = fmaxf(acc, 0.0f);
    }
    __syncthreads();
    if (t < 64) {
        float acc = pb2[t];
        #pragma unroll 8
        for (int i = 0; i < 64; i++) acc = fmaf(sy2[i], pW2[i*64 + t], acc);
        sy[t] = fmaxf(acc, 0.0f);
    }
    __syncthreads();
    if (t < 32) {
        float v = sy[t]*pW3[t] + sy[t+32]*pW3[t+32];
        #pragma unroll
        for (int off = 16; off; off >>= 1) v += __shfl_down_sync(0xffffffffu, v, off);
        if (t == 0) out[b] = v + pb3[0];
    }
}

// ------------------------- host -------------------------
extern "C" void kernel_launch(void* const* d_in, const int* in_sizes, int n_in,
                              void* d_out, int out_size) {
    const float* x         = (const float*)d_in[0];
    const float* edge_attr = (const float*)d_in[1];
    const int*   edge_idx  = (const int*)  d_in[2];
    const int*   batch_map = (const int*)  d_in[3];
    const float* pre_W0 = (const float*)d_in[4];
    const float* pre_b0 = (const float*)d_in[5];
    const float* pre_W1 = (const float*)d_in[6];
    const float* pre_b1 = (const float*)d_in[7];
    const float* pre_W2 = (const float*)d_in[8];
    const float* pre_b2 = (const float*)d_in[9];
    const float* enn_W1 = (const float*)d_in[10];
    const float* enn_b1 = (const float*)d_in[11];
    const float* enn_W2 = (const float*)d_in[12];
    const float* enn_b2 = (const float*)d_in[13];
    const float* root_W = (const float*)d_in[14];
    const float* conv_b = (const float*)d_in[15];
    const float* gru_Wih = (const float*)d_in[16];
    const float* gru_Whh = (const float*)d_in[17];
    const float* gru_bih = (const float*)d_in[18];
    const float* gru_bhh = (const float*)d_in[19];
    const float* s2s_Wih = (const float*)d_in[20];
    const float* s2s_Whh = (const float*)d_in[21];
    const float* s2s_bih = (const float*)d_in[22];
    const float* s2s_bhh = (const float*)d_in[23];
    const float* post_W0 = (const float*)d_in[24];
    const float* post_b0 = (const float*)d_in[25];
    const float* post_W1 = (const float*)d_in[26];
    const float* post_b1 = (const float*)d_in[27];
    const float* post_W2 = (const float*)d_in[28];
    const float* post_b2 = (const float*)d_in[29];
    const float* post_W3 = (const float*)d_in[30];
    const float* post_b3 = (const float*)d_in[31];

    float *bufA, *bufB, *agg, *deg;
    cudaGetSymbolAddress((void**)&bufA, g_bufA);
    cudaGetSymbolAddress((void**)&bufB, g_bufB);
    cudaGetSymbolAddress((void**)&agg,  g_agg);
    cudaGetSymbolAddress((void**)&deg,  g_deg);

    cudaMemsetAsync(deg, 0, NN*sizeof(float));
    cudaMemsetAsync(agg, 0, NN*DD*sizeof(float));

    k_ke3<<<128, 256>>>(enn_W1, enn_b1, edge_attr, edge_idx);
    k_offsets<<<1, 256>>>(batch_map);
    k_scatter3<<<128, 256>>>(edge_attr, edge_idx);
    k_buildPQ3<<<dim3(65, 4, 3), 256>>>(enn_W2, enn_b2);

    k_pre<<<NN/16, 256>>>(x, pre_W0, pre_b0, pre_W1, pre_b1, pre_W2, pre_b2, bufA);

    float* curbuf = bufA;
    float* nxtbuf = bufB;
    for (int l = 0; l < 3; l++) {
        k_msg<<<dim3(8, NK), 256>>>(curbuf, l);
        k_convgru<<<NN/16, 256>>>(curbuf, root_W + l*4096, conv_b + l*64,
                                  gru_Wih + l*64*192, gru_bih + l*192,
                                  gru_Whh + l*64*192, gru_bhh + l*192, nxtbuf);
        float* sw = curbuf; curbuf = nxtbuf; nxtbuf = sw;
    }

    k_s2s<<<BB, 256>>>(curbuf, s2s_Wih, s2s_Whh, s2s_bih, s2s_bhh,
                       post_W0, post_b0, post_W1, post_b1,
                       post_W2, post_b2, post_W3, post_b3, (float*)d_out);
}

// round 6
// speedup vs baseline: 1.5289x; 1.0006x over previous
#include <cuda_runtime.h>
#include <math.h>

#define NN 4096
#define DD 64
#define EE 32768
#define BB 32
#define NK 65   // intervals = 64 breakpoints + 1

// ------------------------- scratch (device globals) -------------------------
__device__ float  g_bufA[NN*DD];
__device__ float  g_bufB[NN*DD];
__device__ float  g_agg[NN*DD];
__device__ float  g_deg[NN];
__device__ float  g_P[3*NK*4096];
__device__ float  g_Q[3*NK*4096];
__device__ float  g_w[3*64], g_c[3*64];
__device__ int    g_rank[3*64];
__device__ int    g_ke[3*EE];
__device__ float4 g_edata[3*EE];
__device__ int    g_bhist[3*NK*128];
__device__ int    g_bbase[3*NK*128];
__device__ int    g_off[3*(NK+1)];
__device__ float  g_e[NN];
__device__ int    g_bstart[BB+1];

__device__ __forceinline__ float sigm(float x) { return 1.0f/(1.0f+expf(-x)); }

// packed f32x2 helpers
__device__ __forceinline__ unsigned long long pk2(float lo, float hi) {
    unsigned long long r;
    asm("mov.b64 %0, {%1, %2};" : "=l"(r) : "f"(lo), "f"(hi));
    return r;
}
__device__ __forceinline__ unsigned long long fma2(unsigned long long a,
                                                   unsigned long long b,
                                                   unsigned long long c) {
    unsigned long long d;
    asm("fma.rn.f32x2 %0, %1, %2, %3;" : "=l"(d) : "l"(a), "l"(b), "l"(c));
    return d;
}
__device__ __forceinline__ void upk2(unsigned long long v, float& lo, float& hi) {
    asm("mov.b64 {%0, %1}, %2;" : "=f"(lo), "=f"(hi) : "l"(v));
}

// ------------------------- edge classification: all 3 layers + deg -------------------------
__global__ __launch_bounds__(256) void k_ke3(const float* __restrict__ W1,
                                             const float* __restrict__ b1,
                                             const float* __restrict__ ea,
                                             const int* __restrict__ eidx) {
    __shared__ float st[64];   // raw breakpoints
    __shared__ float ss[64];   // sorted breakpoints
    __shared__ int   hist[NK];
    int t = threadIdx.x, b = blockIdx.x;
    int e = b*256 + t;
    float a = ea[e];
    atomicAdd(&g_deg[eidx[EE + e]], 1.0f);
    for (int l = 0; l < 3; l++) {
        if (t < NK) hist[t] = 0;
        if (t < 64) {
            float w = W1[l*64 + t], c = b1[l*64 + t];
            float tt = (w != 0.0f) ? (-c / w) : __int_as_float(0x7f800000);
            st[t] = tt;
            if (b == 0) { g_w[l*64 + t] = w; g_c[l*64 + t] = c; }
        }
        __syncthreads();
        if (t < 64) {
            float tt = st[t];
            int r = 0;
            for (int j = 0; j < 64; j++)
                r += (st[j] < tt || (st[j] == tt && j < t)) ? 1 : 0;
            ss[r] = tt;
            if (b == 0) g_rank[l*64 + t] = r;
        }
        __syncthreads();
        int lo = 0, hi = 64;
        while (lo < hi) { int mid = (lo+hi)>>1; if (ss[mid] < a) lo = mid+1; else hi = mid; }
        g_ke[l*EE + e] = lo;
        atomicAdd(&hist[lo], 1);
        __syncthreads();
        if (t < NK) g_bhist[(l*NK + t)*128 + b] = hist[t];
        __syncthreads();
    }
}

// ------------------------- offsets: per-block bases + bucket offsets + bstart -------------------------
__global__ __launch_bounds__(256) void k_offsets(const int* __restrict__ bm) {
    __shared__ int stot[3*NK];
    int t = threadIdx.x, lane = t & 31, warp = t >> 5;
    for (int lk = warp; lk < 3*NK; lk += 8) {
        int4 v = ((const int4*)(g_bhist + lk*128))[lane];
        int p1 = v.x + v.y;
        int p2 = p1 + v.z;
        int tot = p2 + v.w;
        int inc = tot;
        #pragma unroll
        for (int off = 1; off < 32; off <<= 1) {
            int n = __shfl_up_sync(0xffffffffu, inc, off);
            if (lane >= off) inc += n;
        }
        int excl = inc - tot;
        int4 o;
        o.x = excl; o.y = excl + v.x; o.z = excl + p1; o.w = excl + p2;
        ((int4*)(g_bbase + lk*128))[lane] = o;
        if (lane == 31) stot[lk] = inc;
    }
    __syncthreads();
    if (t < 3) {
        int s = 0;
        for (int k = 0; k < NK; k++) { g_off[t*(NK+1) + k] = s; s += stot[t*NK + k]; }
        g_off[t*(NK+1) + NK] = s;
    }
    if (t >= 128 && t <= 128 + BB) {
        int bb = t - 128;
        int lo = 0, hi = NN;
        while (lo < hi) { int mid = (lo+hi)>>1; if (bm[mid] < bb) lo = mid+1; else hi = mid; }
        g_bstart[bb] = lo;
    }
}

// ------------------------- scatter: deterministic, no global atomics -------------------------
__global__ __launch_bounds__(256) void k_scatter3(const float* __restrict__ ea,
                                                  const int* __restrict__ eidx) {
    __shared__ int sbase[NK];
    __shared__ int scnt[NK];
    int t = threadIdx.x, b = blockIdx.x;
    int e = b*256 + t;
    float a = ea[e];
    int s = eidx[e], d = eidx[EE + e];
    float4 rec;
    rec.x = __int_as_float(s);
    rec.y = __int_as_float(d);
    rec.z = a;
    rec.w = 0.0f;
    for (int l = 0; l < 3; l++) {
        if (t < NK) {
            sbase[t] = g_off[l*(NK+1) + t] + g_bbase[(l*NK + t)*128 + b];
            scnt[t] = 0;
        }
        __syncthreads();
        int k = g_ke[l*EE + e];
        int pos = sbase[k] + atomicAdd(&scnt[k], 1);
        g_edata[l*EE + pos] = rec;
        __syncthreads();
    }
}

// ------------------------- build P/Q tables, all 3 layers -------------------------
__global__ __launch_bounds__(256) void k_buildPQ3(const float* __restrict__ W2,
                                                  const float* __restrict__ b2) {
    __shared__ float sw[64], sc[64];
    __shared__ int srk[64];
    int t = threadIdx.x;
    int l = blockIdx.z;
    if (t < 64) { sw[t] = g_w[l*64+t]; sc[t] = g_c[l*64+t]; srk[t] = g_rank[l*64+t]; }
    __syncthreads();
    int k  = blockIdx.x;
    int o0 = blockIdx.y*1024 + t;
    const float* W2l = W2 + l*64*4096;
    const float* b2l = b2 + l*4096;
    float p[4], q[4];
    #pragma unroll
    for (int j = 0; j < 4; j++) { p[j] = b2l[o0 + j*256]; q[j] = 0.0f; }
    for (int g = 0; g < 64; g++) {
        float w = sw[g], c = sc[g];
        bool act = (w > 0.0f) ? (srk[g] < k)
                 : ((w < 0.0f) ? (srk[g] >= k) : (c > 0.0f));
        if (!act) continue;
        const float* row = W2l + g*4096 + o0;
        #pragma unroll
        for (int j = 0; j < 4; j++) {
            float v = row[j*256];
            p[j] = fmaf(c, v, p[j]);
            q[j] = fmaf(w, v, q[j]);
        }
    }
    int base = (l*NK + k)*4096 + o0;
    #pragma unroll
    for (int j = 0; j < 4; j++) {
        g_P[base + j*256] = p[j];
        g_Q[base + j*256] = q[j];
    }
}

// ------------------------- fused 3-layer pre-MLP -------------------------
__global__ __launch_bounds__(256) void k_pre(const float* __restrict__ x,
                                             const float* __restrict__ W0, const float* __restrict__ b0,
                                             const float* __restrict__ W1, const float* __restrict__ b1,
                                             const float* __restrict__ W2, const float* __restrict__ b2,
                                             float* __restrict__ Y) {
    __shared__ float sW[8192];
    __shared__ float sA[2048];
    __shared__ float sT[1024];
    int t = threadIdx.x;
    int r0 = blockIdx.x * 16;
    for (int i = t; i < 2048; i += 256) sA[i] = x[r0*128 + i];
    for (int i = t; i < 8192; i += 256) sW[i] = W0[i];
    __syncthreads();
    int o = t & 63, mq = t >> 6;
    {
        float bv = b0[o];
        float a0 = bv, a1 = bv, a2 = bv, a3 = bv;
        #pragma unroll 4
        for (int i = 0; i < 128; i++) {
            float wv = sW[i*64 + o];
            a0 = fmaf(sA[(mq+ 0)*128 + i], wv, a0);
            a1 = fmaf(sA[(mq+ 4)*128 + i], wv, a1);
            a2 = fmaf(sA[(mq+ 8)*128 + i], wv, a2);
            a3 = fmaf(sA[(mq+12)*128 + i], wv, a3);
        }
        sT[(mq+ 0)*64+o] = fmaxf(a0, 0.0f);
        sT[(mq+ 4)*64+o] = fmaxf(a1, 0.0f);
        sT[(mq+ 8)*64+o] = fmaxf(a2, 0.0f);
        sT[(mq+12)*64+o] = fmaxf(a3, 0.0f);
    }
    __syncthreads();
    for (int i = t; i < 4096; i += 256) sW[i] = W1[i];
    __syncthreads();
    {
        float bv = b1[o];
        float a0 = bv, a1 = bv, a2 = bv, a3 = bv;
        #pragma unroll 4
        for (int i = 0; i < 64; i++) {
            float wv = sW[i*64 + o];
            a0 = fmaf(sT[(mq+ 0)*64 + i], wv, a0);
            a1 = fmaf(sT[(mq+ 4)*64 + i], wv, a1);
            a2 = fmaf(sT[(mq+ 8)*64 + i], wv, a2);
            a3 = fmaf(sT[(mq+12)*64 + i], wv, a3);
        }
        sA[(mq+ 0)*64+o] = fmaxf(a0, 0.0f);
        sA[(mq+ 4)*64+o] = fmaxf(a1, 0.0f);
        sA[(mq+ 8)*64+o] = fmaxf(a2, 0.0f);
        sA[(mq+12)*64+o] = fmaxf(a3, 0.0f);
    }
    __syncthreads();
    for (int i = t; i < 4096; i += 256) sW[i] = W2[i];
    __syncthreads();
    {
        float bv = b2[o];
        float a0 = bv, a1 = bv, a2 = bv, a3 = bv;
        #pragma unroll 4
        for (int i = 0; i < 64; i++) {
            float wv = sW[i*64 + o];
            a0 = fmaf(sA[(mq+ 0)*64 + i], wv, a0);
            a1 = fmaf(sA[(mq+ 4)*64 + i], wv, a1);
            a2 = fmaf(sA[(mq+ 8)*64 + i], wv, a2);
            a3 = fmaf(sA[(mq+12)*64 + i], wv, a3);
        }
        Y[(r0+mq+ 0)*64+o] = fmaxf(a0, 0.0f);
        Y[(r0+mq+ 4)*64+o] = fmaxf(a1, 0.0f);
        Y[(r0+mq+ 8)*64+o] = fmaxf(a2, 0.0f);
        Y[(r0+mq+12)*64+o] = fmaxf(a3, 0.0f);
    }
}

// ------------------------- warp-per-edge message (f32x2 packed) -------------------------
__global__ __launch_bounds__(256) void k_msg(const float* __restrict__ X, int l) {
    // paired layout: element (row i, lane o) pairs outputs (o, o+32) adjacently
    __shared__ float sP2[4096];
    __shared__ float sQ2[4096];
    int t = threadIdx.x;
    int k = blockIdx.y;
    int beg = g_off[l*(NK+1) + k];
    int end = g_off[l*(NK+1) + k + 1];
    if (beg == end) return;
    const float* P = g_P + (l*NK + k)*4096;
    const float* Q = g_Q + (l*NK + k)*4096;
    for (int i = t; i < 4096; i += 256) {
        int row = i >> 6, col = i & 63;
        int o = col & 31, half = col >> 5;
        int dstidx = (row*32 + o)*2 + half;
        sP2[dstidx] = P[i];
        sQ2[dstidx] = Q[i];
    }
    __syncthreads();
    int warp = t >> 5, lane = t & 31;
    int stride = gridDim.x * 8;
    const float2* X2 = (const float2*)X;
    for (int idx = beg + blockIdx.x*8 + warp; idx < end; idx += stride) {
        float4 rec = g_edata[l*EE + idx];
        int s  = __float_as_int(rec.x);
        int dn = __float_as_int(rec.y);
        float a = rec.z;
        unsigned long long apack = pk2(a, a);
        float2 xv = X2[s*32 + lane];
        unsigned long long acc = pk2(0.0f, 0.0f);
        #pragma unroll
        for (int i = 0; i < 64; i += 2) {
            float xa = __shfl_sync(0xffffffffu, xv.x, i >> 1);
            float xb = __shfl_sync(0xffffffffu, xv.y, i >> 1);
            {
                const float2* pp = (const float2*)&sP2[(i*32 + lane)*2];
                const float2* qq = (const float2*)&sQ2[(i*32 + lane)*2];
                float2 p = *pp, q = *qq;
                unsigned long long m = fma2(apack, pk2(q.x, q.y), pk2(p.x, p.y));
                acc = fma2(pk2(xa, xa), m, acc);
            }
            {
                const float2* pp = (const float2*)&sP2[((i+1)*32 + lane)*2];
                const float2* qq = (const float2*)&sQ2[((i+1)*32 + lane)*2];
                float2 p = *pp, q = *qq;
                unsigned long long m = fma2(apack, pk2(q.x, q.y), pk2(p.x, p.y));
                acc = fma2(pk2(xb, xb), m, acc);
            }
        }
        float acc0, acc1;
        upk2(acc, acc0, acc1);
        atomicAdd(&g_agg[dn*64 + lane],      acc0);
        atomicAdd(&g_agg[dn*64 + lane + 32], acc1);
    }
}

// ------------------------- fused conv + GRU (self-cleans g_agg) -------------------------
__global__ __launch_bounds__(256) void k_convgru(const float* __restrict__ X,
                                                 const float* __restrict__ rootW,
                                                 const float* __restrict__ cb,
                                                 const float* __restrict__ Wih,
                                                 const float* __restrict__ bih,
                                                 const float* __restrict__ Whh,
                                                 const float* __restrict__ bhh,
                                                 float* __restrict__ Y) {
    __shared__ float sH[1024];
    __shared__ float sConv[1024];
    __shared__ float sBig[6144];
    int t = threadIdx.x;
    int r0 = blockIdx.x * 16;
    for (int i = t; i < 1024; i += 256) sH[i] = X[r0*64 + i];
    for (int i = t; i < 4096; i += 256) sBig[i] = rootW[i];
    __syncthreads();
    int o = t & 63, mq = t >> 6;
    {
        float bv = cb[o];
        int n0 = r0 + mq;
        float a0 = fmaf(g_agg[(n0+ 0)*64+o], 1.0f/fmaxf(g_deg[n0+ 0], 1.0f), bv);
        float a1 = fmaf(g_agg[(n0+ 4)*64+o], 1.0f/fmaxf(g_deg[n0+ 4], 1.0f), bv);
        float a2 = fmaf(g_agg[(n0+ 8)*64+o], 1.0f/fmaxf(g_deg[n0+ 8], 1.0f), bv);
        float a3 = fmaf(g_agg[(n0+12)*64+o], 1.0f/fmaxf(g_deg[n0+12], 1.0f), bv);
        // self-clean agg for the next layer
        g_agg[(n0+ 0)*64+o] = 0.0f;
        g_agg[(n0+ 4)*64+o] = 0.0f;
        g_agg[(n0+ 8)*64+o] = 0.0f;
        g_agg[(n0+12)*64+o] = 0.0f;
        #pragma unroll 4
        for (int i = 0; i < 64; i++) {
            float wv = sBig[i*64 + o];
            a0 = fmaf(sH[(mq+ 0)*64 + i], wv, a0);
            a1 = fmaf(sH[(mq+ 4)*64 + i], wv, a1);
            a2 = fmaf(sH[(mq+ 8)*64 + i], wv, a2);
            a3 = fmaf(sH[(mq+12)*64 + i], wv, a3);
        }
        sConv[(mq+ 0)*64+o] = fmaxf(a0, 0.0f);
        sConv[(mq+ 4)*64+o] = fmaxf(a1, 0.0f);
        sConv[(mq+ 8)*64+o] = fmaxf(a2, 0.0f);
        sConv[(mq+12)*64+o] = fmaxf(a3, 0.0f);
    }
    __syncthreads();
    if (t < 192) {
        float gi[16], gh[16];
        float bi = bih[t], bh = bhh[t];
        #pragma unroll
        for (int m = 0; m < 16; m++) { gi[m] = bi; gh[m] = bh; }
        #pragma unroll 4
        for (int kk = 0; kk < 64; kk++) {
            float wi = Wih[kk*192 + t];
            float wh = Whh[kk*192 + t];
            #pragma unroll
            for (int m = 0; m < 16; m++) {
                gi[m] = fmaf(sConv[m*64 + kk], wi, gi[m]);
                gh[m] = fmaf(sH[m*64 + kk],    wh, gh[m]);
            }
        }
        #pragma unroll
        for (int m = 0; m < 16; m++) {
            sBig[m*192 + t]        = gi[m];
            sBig[3072 + m*192 + t] = gh[m];
        }
    }
    __syncthreads();
    #pragma unroll
    for (int j = 0; j < 4; j++) {
        int idx = t + j*256;
        int m = idx >> 6, d = idx & 63;
        float ir = sBig[m*192+d],      iz = sBig[m*192+64+d],      inn = sBig[m*192+128+d];
        float hr = sBig[3072+m*192+d], hz = sBig[3072+m*192+64+d], hn  = sBig[3072+m*192+128+d];
        float r = sigm(ir + hr);
        float z = sigm(iz + hz);
        float nv = tanhf(inn + r * hn);
        float h = sH[m*64 + d];
        Y[(r0+m)*64 + d] = (1.0f - z) * nv + z * h;
    }
}

// ------------------------- fused Set2Set (3 steps) + post-MLP + final -------------------------
__global__ __launch_bounds__(256) void k_s2s(const float* __restrict__ X,
                                             const float* __restrict__ Wih,
                                             const float* __restrict__ Whh,
                                             const float* __restrict__ bih,
                                             const float* __restrict__ bhh,
                                             const float* __restrict__ pW0, const float* __restrict__ pb0,
                                             const float* __restrict__ pW1, const float* __restrict__ pb1,
                                             const float* __restrict__ pW2, const float* __restrict__ pb2,
                                             const float* __restrict__ pW3, const float* __restrict__ pb3,
                                             float* __restrict__ out) {
    __shared__ float sqs[128];
    __shared__ float shh[64], scc[64];
    __shared__ float sg[256];
    __shared__ float sred[256];
    __shared__ float smax, sden;
    __shared__ float sy[64], sy2[64];
    int b = blockIdx.x;
    int t = threadIdx.x;
    int beg = g_bstart[b], end = g_bstart[b+1];
    if (t < 128) sqs[t] = 0.0f;
    if (t < 64) { shh[t] = 0.0f; scc[t] = 0.0f; }
    __syncthreads();
    for (int step = 0; step < 3; step++) {
        float acc0 = bih[t] + bhh[t], acc1 = 0.0f;
        #pragma unroll 8
        for (int i = 0; i < 128; i += 2) {
            acc0 = fmaf(sqs[i],   Wih[i*256 + t],     acc0);
            acc1 = fmaf(sqs[i+1], Wih[(i+1)*256 + t], acc1);
        }
        #pragma unroll 8
        for (int i = 0; i < 64; i += 2) {
            acc0 = fmaf(shh[i],   Whh[i*256 + t],     acc0);
            acc1 = fmaf(shh[i+1], Whh[(i+1)*256 + t], acc1);
        }
        sg[t] = acc0 + acc1;
        __syncthreads();
        if (t < 64) {
            float c = sigm(sg[64+t]) * scc[t] + sigm(sg[t]) * tanhf(sg[128+t]);
            float h = sigm(sg[192+t]) * tanhf(c);
            scc[t] = c; shh[t] = h;
        }
        __syncthreads();
        int warp = t >> 5, lane = t & 31;
        float mloc = -3.4e38f;
        for (int n = beg + warp; n < end; n += 8) {
            float v = X[n*64 + lane]*shh[lane] + X[n*64 + 32 + lane]*shh[32 + lane];
            #pragma unroll
            for (int off = 16; off; off >>= 1) v += __shfl_down_sync(0xffffffffu, v, off);
            v = __shfl_sync(0xffffffffu, v, 0);
            if (lane == 0) g_e[n] = v;
            mloc = fmaxf(mloc, v);
        }
        if (lane == 0) sred[warp] = mloc;
        __syncthreads();
        if (t == 0) {
            float m = sred[0];
            for (int j = 1; j < 8; j++) m = fmaxf(m, sred[j]);
            smax = m;
        }
        __syncthreads();
        float m = smax;
        float dl = 0.0f;
        for (int n = beg + t; n < end; n += 256) dl += expf(g_e[n] - m);
        sred[t] = dl;
        __syncthreads();
        if (t < 128) sred[t] += sred[t+128];
        __syncthreads();
        if (t < 64) sred[t] += sred[t+64];
        __syncthreads();
        if (t == 0) { float s = 0.0f; for (int j = 0; j < 64; j++) s += sred[j]; sden = s; }
        __syncthreads();
        float den = sden;
        int d = t & 63, quarter = t >> 6;
        float ra = 0.0f;
        for (int n = beg + quarter; n < end; n += 4) ra += expf(g_e[n] - m) * X[n*64 + d];
        __syncthreads();
        sred[t] = ra;
        __syncthreads();
        if (t < 64) {
            sqs[64 + t] = (sred[t] + sred[t+64] + sred[t+128] + sred[t+192]) / den;
            sqs[t]      = shh[t];
        }
        __syncthreads();
    }
    if (t < 64) {
        float acc = pb0[t];
        #pragma unroll 8
        for (int i = 0; i < 128; i++) acc = fmaf(sqs[i], pW0[i*64 + t], acc);
        sy[t] = fmaxf(acc, 0.0f);
    }
    __syncthreads();
    if (t < 64) {
        float acc = pb1[t];
        #pragma unroll 8
        for (int i = 0; i < 64; i++) acc = fmaf(sy[i], pW1[i*64 + t], acc);
        sy2[t] = fmaxf(acc, 0.0f);
    }
    __syncthreads();
    if (t < 64) {
        float acc = pb2[t];
        #pragma unroll 8
        for (int i = 0; i < 64; i++) acc = fmaf(sy2[i], pW2[i*64 + t], acc);
        sy[t] = fmaxf(acc, 0.0f);
    }
    __syncthreads();
    if (t < 32) {
        float v = sy[t]*pW3[t] + sy[t+32]*pW3[t+32];
        #pragma unroll
        for (int off = 16; off; off >>= 1) v += __shfl_down_sync(0xffffffffu, v, off);
        if (t == 0) out[b] = v + pb3[0];
    }
}

// ------------------------- host -------------------------
extern "C" void kernel_launch(void* const* d_in, const int* in_sizes, int n_in,
                              void* d_out, int out_size) {
    const float* x         = (const float*)d_in[0];
    const float* edge_attr = (const float*)d_in[1];
    const int*   edge_idx  = (const int*)  d_in[2];
    const int*   batch_map = (const int*)  d_in[3];
    const float* pre_W0 = (const float*)d_in[4];
    const float* pre_b0 = (const float*)d_in[5];
    const float* pre_W1 = (const float*)d_in[6];
    const float* pre_b1 = (const float*)d_in[7];
    const float* pre_W2 = (const float*)d_in[8];
    const float* pre_b2 = (const float*)d_in[9];
    const float* enn_W1 = (const float*)d_in[10];
    const float* enn_b1 = (const float*)d_in[11];
    const float* enn_W2 = (const float*)d_in[12];
    const float* enn_b2 = (const float*)d_in[13];
    const float* root_W = (const float*)d_in[14];
    const float* conv_b = (const float*)d_in[15];
    const float* gru_Wih = (const float*)d_in[16];
    const float* gru_Whh = (const float*)d_in[17];
    const float* gru_bih = (const float*)d_in[18];
    const float* gru_bhh = (const float*)d_in[19];
    const float* s2s_Wih = (const float*)d_in[20];
    const float* s2s_Whh = (const float*)d_in[21];
    const float* s2s_bih = (const float*)d_in[22];
    const float* s2s_bhh = (const float*)d_in[23];
    const float* post_W0 = (const float*)d_in[24];
    const float* post_b0 = (const float*)d_in[25];
    const float* post_W1 = (const float*)d_in[26];
    const float* post_b1 = (const float*)d_in[27];
    const float* post_W2 = (const float*)d_in[28];
    const float* post_b2 = (const float*)d_in[29];
    const float* post_W3 = (const float*)d_in[30];
    const float* post_b3 = (const float*)d_in[31];

    float *bufA, *bufB, *agg, *deg;
    cudaGetSymbolAddress((void**)&bufA, g_bufA);
    cudaGetSymbolAddress((void**)&bufB, g_bufB);
    cudaGetSymbolAddress((void**)&agg,  g_agg);
    cudaGetSymbolAddress((void**)&deg,  g_deg);

    cudaMemsetAsync(deg, 0, NN*sizeof(float));
    cudaMemsetAsync(agg, 0, NN*DD*sizeof(float));

    k_ke3<<<128, 256>>>(enn_W1, enn_b1, edge_attr, edge_idx);
    k_offsets<<<1, 256>>>(batch_map);
    k_scatter3<<<128, 256>>>(edge_attr, edge_idx);
    k_buildPQ3<<<dim3(65, 4, 3), 256>>>(enn_W2, enn_b2);

    k_pre<<<NN/16, 256>>>(x, pre_W0, pre_b0, pre_W1, pre_b1, pre_W2, pre_b2, bufA);

    float* curbuf = bufA;
    float* nxtbuf = bufB;
    for (int l = 0; l < 3; l++) {
        k_msg<<<dim3(8, NK), 256>>>(curbuf, l);
        k_convgru<<<NN/16, 256>>>(curbuf, root_W + l*4096, conv_b + l*64,
                                  gru_Wih + l*64*192, gru_bih + l*192,
                                  gru_Whh + l*64*192, gru_bhh + l*192, nxtbuf);
        float* sw = curbuf; curbuf = nxtbuf; nxtbuf = sw;
    }

    k_s2s<<<BB, 256>>>(curbuf, s2s_Wih, s2s_Whh, s2s_bih, s2s_bhh,
                       post_W0, post_b0, post_W1, post_b1,
                       post_W2, post_b2, post_W3, post_b3, (float*)d_out);
}